// round 14
// baseline (speedup 1.0000x reference)
#include <cuda_runtime.h>
#include <cuda_bf16.h>
#include <math.h>
#include <stdint.h>

#define BB 4
#define CC 256
#define HWX 16384
#define HF 128
#define WF 65
#define FF (HF*WF)
#define NB 6
#define GH 128
#define SP 129

typedef unsigned long long ull;

__device__ float  g_xt[(size_t)BB*CC*HWX];
__device__ float2 g_Xf[(size_t)BB*CC*FF];
__device__ float2 g_Xmap[(size_t)BB*CC*FF];
__device__ float  g_yspec[(size_t)BB*CC*HWX];
__device__ float  g_yst[(size_t)BB*CC*HWX];
__device__ __nv_bfloat16 g_xhi[(size_t)BB*CC*HWX];
__device__ __nv_bfloat16 g_xlo[(size_t)BB*CC*HWX];
__device__ __nv_bfloat16 g_whi[CC*CC];
__device__ __nv_bfloat16 g_wlo[CC*CC];
__device__ __nv_bfloat16 g_wrh[CC*CC];
__device__ __nv_bfloat16 g_wrl[CC*CC];
__device__ __nv_bfloat16 g_wih[CC*CC];
__device__ __nv_bfloat16 g_wil[CC*CC];
__device__ float  g_alpha[BB*CC*NB];
__device__ int    g_bid[FF];
__device__ float  g_cnt[NB];

__device__ __forceinline__ float2 cmul(float2 a, float2 b){return make_float2(a.x*b.x-a.y*b.y,a.x*b.y+a.y*b.x);}
__device__ __forceinline__ float2 cadd(float2 a, float2 b){return make_float2(a.x+b.x,a.y+b.y);}
__device__ __forceinline__ float2 csub(float2 a, float2 b){return make_float2(a.x-b.x,a.y-b.y);}
__device__ __forceinline__ int brev7(int x){return (int)(__brev((unsigned)x)>>25);}
__device__ __forceinline__ float sigm(float x){return 1.0f/(1.0f+expf(-x));}

__device__ __forceinline__ uint32_t smem_u32(const void* p){
    uint32_t a;asm("{ .reg .u64 t; cvta.to.shared.u64 t, %1; cvt.u32.u64 %0, t; }":"=r"(a):"l"(p));return a;
}
#define LDM4(d,adr) asm volatile("ldmatrix.sync.aligned.m8n8.x4.shared.b16 {%0,%1,%2,%3},[%4];" \
    :"=r"((d)[0]),"=r"((d)[1]),"=r"((d)[2]),"=r"((d)[3]):"r"(adr))
#define MMA16816(d,a,b0,b1) asm volatile( \
    "mma.sync.aligned.m16n8k16.row.col.f32.bf16.bf16.f32 {%0,%1,%2,%3},{%4,%5,%6,%7},{%8,%9},{%0,%1,%2,%3};" \
    : "+f"((d)[0]),"+f"((d)[1]),"+f"((d)[2]),"+f"((d)[3]) \
    : "r"((a)[0]),"r"((a)[1]),"r"((a)[2]),"r"((a)[3]),"r"(b0),"r"(b1))
#define CPA16(dst,src) asm volatile("cp.async.cg.shared.global [%0],[%1],16;"::"r"(dst),"l"(src))
#define CPA_COMMIT()   asm volatile("cp.async.commit_group;":::"memory")
#define CPA_WAIT(n)    asm volatile("cp.async.wait_group %0;"::"n"(n):"memory")

/* band table: bit-exact float32 replica of the numpy band partition */
__global__ void k_init(){
    __shared__ int cnt[NB];
    int tid=threadIdx.x;
    if(tid<NB) cnt[tid]=0;
    __syncthreads();
    const float rmax=__fsqrt_rn(2.0f);
    for(int f=tid;f<FF;f+=blockDim.x){
        int h=f/WF, w=f-(f/WF)*WF;
        float a=__fdiv_rn((float)h,127.0f);
        float b=__fdiv_rn((float)w,64.0f);
        float s=__fadd_rn(__fmul_rn(a,a),__fmul_rn(b,b));
        float r=__fsqrt_rn(s);
        float rn=__fdiv_rn(r,rmax);
        int bd=(int)floorf(__fmul_rn(rn,6.0f));
        if(bd>NB-1) bd=NB-1;
        g_bid[f]=bd;
        atomicAdd(&cnt[bd],1);
    }
    __syncthreads();
    if(tid<NB) g_cnt[tid]=(float)max(cnt[tid],1);
}

/* (B,HW,C) -> (B,C,HW), fused bf16 hi/lo split kept in (B,HW,C) */
__global__ void k_transpose(const float* __restrict__ x){
    __shared__ float t[32][33];
    int b=blockIdx.z, p0=blockIdx.x*32, c0=blockIdx.y*32;
    int tx=threadIdx.x, ty=threadIdx.y;
#pragma unroll
    for(int i=0;i<32;i+=8){
        size_t idx=((size_t)b*HWX+(p0+ty+i))*CC+c0+tx;
        float v=x[idx];
        t[ty+i][tx]=v;
        __nv_bfloat16 h=__float2bfloat16(v);
        g_xhi[idx]=h;
        g_xlo[idx]=__float2bfloat16(v-__bfloat162float(h));
    }
    __syncthreads();
#pragma unroll
    for(int i=0;i<32;i+=8) g_xt[((size_t)b*CC+(c0+ty+i))*HWX+p0+tx]=t[tx][ty+i];
}

/* split all three weight matrices in one launch */
__global__ void k_split3(const float* __restrict__ w0,const float* __restrict__ w1,const float* __restrict__ w2){
    int i=blockIdx.x*blockDim.x+threadIdx.x;
    int m=i>>16, r=i&65535;
    if(m>2) return;
    const float* src=(m==0)?w0:(m==1)?w1:w2;
    __nv_bfloat16* hi=(m==0)?g_whi:(m==1)?g_wrh:g_wih;
    __nv_bfloat16* lo=(m==0)?g_wlo:(m==1)?g_wrl:g_wil;
    float v=src[r];
    __nv_bfloat16 h=__float2bfloat16(v);
    hi[r]=h;
    lo[r]=__float2bfloat16(v-__bfloat162float(h));
}

/* (B,C,HW) -> (B,HW,C) for yspec */
__global__ void k_transb(){
    __shared__ float t[32][33];
    int b=blockIdx.z, p0=blockIdx.x*32, c0=blockIdx.y*32;
    int tx=threadIdx.x, ty=threadIdx.y;
#pragma unroll
    for(int i=0;i<32;i+=8) t[ty+i][tx]=g_yspec[((size_t)b*CC+(c0+ty+i))*HWX+p0+tx];
    __syncthreads();
#pragma unroll
    for(int i=0;i<32;i+=8) g_yst[((size_t)b*HWX+(p0+ty+i))*CC+c0+tx]=t[tx][ty+i];
}

/* ---- radix-8 triple-stage butterflies (DIT rows / DIF cols) ---- */
__device__ __forceinline__ void dit8(float2* S,const float2* tw,int base,int half,int j,int s){
    float2 x0=S[base],x1=S[base+half],x2=S[base+2*half],x3=S[base+3*half];
    float2 x4=S[base+4*half],x5=S[base+5*half],x6=S[base+6*half],x7=S[base+7*half];
    float2 w1=tw[j<<(6-s)];
    float2 t1=cmul(w1,x1),t3=cmul(w1,x3),t5=cmul(w1,x5),t7=cmul(w1,x7);
    float2 a0=cadd(x0,t1),a1=csub(x0,t1),a2=cadd(x2,t3),a3=csub(x2,t3);
    float2 a4=cadd(x4,t5),a5=csub(x4,t5),a6=cadd(x6,t7),a7=csub(x6,t7);
    float2 w2a=tw[j<<(5-s)],w2b=tw[(j+half)<<(5-s)];
    float2 u2=cmul(w2a,a2),u3=cmul(w2b,a3),u6=cmul(w2a,a6),u7=cmul(w2b,a7);
    float2 b0=cadd(a0,u2),b2=csub(a0,u2),b1=cadd(a1,u3),b3=csub(a1,u3);
    float2 b4=cadd(a4,u6),b6=csub(a4,u6),b5=cadd(a5,u7),b7=csub(a5,u7);
    float2 w30=tw[j<<(4-s)],w31=tw[(j+half)<<(4-s)],w32=tw[(j+2*half)<<(4-s)],w33=tw[(j+3*half)<<(4-s)];
    float2 v4=cmul(w30,b4),v5=cmul(w31,b5),v6=cmul(w32,b6),v7=cmul(w33,b7);
    S[base]=cadd(b0,v4);        S[base+4*half]=csub(b0,v4);
    S[base+half]=cadd(b1,v5);   S[base+5*half]=csub(b1,v5);
    S[base+2*half]=cadd(b2,v6); S[base+6*half]=csub(b2,v6);
    S[base+3*half]=cadd(b3,v7); S[base+7*half]=csub(b3,v7);
}
__device__ __forceinline__ void dif8(float2* S,const float2* tw,int i0,int strd,int j,int hs,int stp){
    float2 x0=S[i0],x1=S[i0+hs*strd],x2=S[i0+2*hs*strd],x3=S[i0+3*hs*strd];
    float2 x4=S[i0+4*hs*strd],x5=S[i0+5*hs*strd],x6=S[i0+6*hs*strd],x7=S[i0+7*hs*strd];
    float2 a0=cadd(x0,x4), a4=cmul(tw[(j     )<<(6-stp)],csub(x0,x4));
    float2 a1=cadd(x1,x5), a5=cmul(tw[(j+hs  )<<(6-stp)],csub(x1,x5));
    float2 a2=cadd(x2,x6), a6=cmul(tw[(j+2*hs)<<(6-stp)],csub(x2,x6));
    float2 a3=cadd(x3,x7), a7=cmul(tw[(j+3*hs)<<(6-stp)],csub(x3,x7));
    float2 wb0=tw[j<<(7-stp)], wb1=tw[(j+hs)<<(7-stp)];
    float2 b0=cadd(a0,a2), b2=cmul(wb0,csub(a0,a2));
    float2 b1=cadd(a1,a3), b3=cmul(wb1,csub(a1,a3));
    float2 b4=cadd(a4,a6), b6=cmul(wb0,csub(a4,a6));
    float2 b5=cadd(a5,a7), b7=cmul(wb1,csub(a5,a7));
    float2 wc=tw[j<<(8-stp)];
    S[i0]=cadd(b0,b1);           S[i0+hs*strd]=cmul(wc,csub(b0,b1));
    S[i0+2*hs*strd]=cadd(b2,b3); S[i0+3*hs*strd]=cmul(wc,csub(b2,b3));
    S[i0+4*hs*strd]=cadd(b4,b5); S[i0+5*hs*strd]=cmul(wc,csub(b4,b5));
    S[i0+6*hs*strd]=cadd(b6,b7); S[i0+7*hs*strd]=cmul(wc,csub(b6,b7));
}

/* -------- forward: packed complex FFT2 of (c, c+1) plane pair + band sums + fused gate MLP -------- */
__global__ void __launch_bounds__(512) k_fft_fwd(const float* __restrict__ mw1,const float* __restrict__ mb1,
                                                  const float* __restrict__ mw2,const float* __restrict__ mb2){
    extern __shared__ __align__(16) float2 sm[];
    float2* S=sm; float2* tw=sm+128*SP;
    __shared__ float wsum[16][2*NB];
    __shared__ float means[2*NB], hb[2*GH];
    int tid=threadIdx.x;
    int lane=tid&31, wid=tid>>5;
    int bc0=blockIdx.x*2;
    const float* x0=g_xt+(size_t)bc0*HWX;
    const float* x1=x0+HWX;
    if(tid<64){float s,c;sincospif(-(float)tid/64.0f,&s,&c);tw[tid]=make_float2(c,s);}
    for(int idx=tid;idx<HWX;idx+=512){
        int h=idx>>7, w=idx&127;
        S[h*SP+brev7(w)]=make_float2(x0[idx],x1[idx]);
    }
    __syncthreads();
    for(int s=0;s<6;s+=3){
        int half=1<<s;
        for(int q=tid;q<2048;q+=512){
            int row=q&127, c=q>>7;
            int j=c&(half-1), g=c>>s;
            dit8(S,tw,row*SP+g*(half<<3)+j,half,j,s);
        }
        __syncthreads();
    }
    for(int q=tid;q<8192;q+=512){
        int row=q&127, j=q>>7;
        int i0=row*SP+j, i1=i0+64;
        float2 wv=tw[j];
        float2 u=S[i0], v=cmul(wv,S[i1]);
        S[i0]=cadd(u,v); S[i1]=csub(u,v);
    }
    __syncthreads();
    for(int stp=6;stp>=3;stp-=3){
        int hs=1<<(stp-2);
        for(int q=tid;q<2048;q+=512){
            int col=q&127, c=q>>7;
            int j=c&(hs-1), g=c>>(stp-2);
            dif8(S,tw,(g*(hs<<3)+j)*SP+col,SP,j,hs,stp);
        }
        __syncthreads();
    }
    for(int q=tid;q<8192;q+=512){
        int col=q&127, g=q>>7;
        int i0=(2*g)*SP+col, i1=i0+SP;
        float2 u=S[i0], v=S[i1];
        S[i0]=cadd(u,v); S[i1]=csub(u,v);
    }
    __syncthreads();
    float acc[2*NB];
#pragma unroll
    for(int k=0;k<2*NB;++k) acc[k]=0.0f;
    const float hs2=0.5f/128.0f;
    float2* Xo0=g_Xf+(size_t)bc0*FF;
    float2* Xo1=Xo0+FF;
    for(int idx=tid;idx<FF;idx+=512){
        int hf=idx/WF, w=idx-hf*WF;
        float2 Z1=S[brev7(hf)*SP+w];
        int h2=(128-hf)&127, w2=(128-w)&127;
        float2 Z2=S[brev7(h2)*SP+w2];
        float2 v0=make_float2((Z1.x+Z2.x)*hs2,(Z1.y-Z2.y)*hs2);
        float2 v1=make_float2((Z1.y+Z2.y)*hs2,(Z2.x-Z1.x)*hs2);
        Xo0[idx]=v0; Xo1[idx]=v1;
        float m0=sqrtf(v0.x*v0.x+v0.y*v0.y);
        float m1=sqrtf(v1.x*v1.x+v1.y*v1.y);
        int bd=g_bid[idx];
#pragma unroll
        for(int k=0;k<NB;++k){
            acc[k]   +=(bd==k)?m0:0.0f;
            acc[NB+k]+=(bd==k)?m1:0.0f;
        }
    }
#pragma unroll
    for(int k=0;k<2*NB;++k){
        float v=acc[k];
#pragma unroll
        for(int o=16;o;o>>=1) v+=__shfl_xor_sync(0xffffffffu,v,o);
        if(lane==0) wsum[wid][k]=v;
    }
    __syncthreads();
    if(tid<2*NB){
        float s=0.0f;
#pragma unroll
        for(int w=0;w<16;++w) s+=wsum[w][tid];
        int k=tid%NB;
        means[tid]=s/(g_cnt[k]+1e-6f);
    }
    __syncthreads();
    if(tid<2*GH){
        int ch=tid>>7, hh=tid&127;
        float hv=mb1[hh];
#pragma unroll
        for(int n=0;n<NB;++n) hv+=mw1[hh*NB+n]*means[ch*NB+n];
        hb[tid]=fmaxf(hv,0.0f);
    }
    __syncthreads();
    if(wid<2*NB){
        int ch=wid/NB, n=wid-ch*NB;
        float v=0.0f;
#pragma unroll
        for(int i=0;i<4;++i){int hh=lane+32*i; v+=mw2[n*GH+hh]*hb[ch*GH+hh];}
#pragma unroll
        for(int o=16;o;o>>=1) v+=__shfl_xor_sync(0xffffffffu,v,o);
        if(lane==0) g_alpha[(bc0+ch)*NB+n]=1.0f/(1.0f+expf(-(v+mb2[n])));
    }
}

/* ---------------- HMMA complex GEMM on masked freqs ---------------- */
#define CG_XRH 0
#define CG_XRL 5120
#define CG_XIH 10240
#define CG_XIL 15360
#define CG_W   20480
#define CG_SMEM 81920

__global__ void __launch_bounds__(256) k_cgemm_hmma(const float* __restrict__ kxp,const float* __restrict__ kyp){
    extern __shared__ __align__(16) char smc[];
    int kxi=(int)floorf(sigm(kxp[0])*128.0f);
    int kyi=(int)floorf(sigm(kyp[0])*65.0f);
    int NC=kxi*kyi;
    int f0=blockIdx.x*64;
    if(f0>=NC) return;
    int c0=blockIdx.y*128, b=blockIdx.z;
    __shared__ int fmap[64];
    int tid=threadIdx.x, lane=tid&31, wid=tid>>5;
    int warp_m=wid&1, warp_n=wid>>1;
    if(tid<64){
        int f=f0+tid;
        fmap[tid]=(f<NC)?((f/kyi)*WF+(f-(f/kyi)*kyi)):-1;
    }
    __nv_bfloat16* sX=(__nv_bfloat16*)smc;
    uint32_t uX=smem_u32(smc);
    float accR[2][4][4], accI[2][4][4];
#pragma unroll
    for(int i=0;i<2;++i)
#pragma unroll
        for(int j=0;j<4;++j)
#pragma unroll
            for(int k=0;k<4;++k){accR[i][j][k]=0.0f;accI[i][j][k]=0.0f;}
    __syncthreads();

    const __nv_bfloat16* gW[4]={g_wrh,g_wrl,g_wih,g_wil};
    for(int kc=0;kc<8;++kc){
        int k0=kc*32;
        {
            int fi=tid&63, ds=tid>>6;
            int mp=fmap[fi];
#pragma unroll
            for(int i=0;i<8;++i){
                int d=ds*8+i;
                float2 v=make_float2(0.0f,0.0f);
                if(mp>=0) v=g_Xf[((size_t)(b*CC+k0+d))*FF+mp];
                __nv_bfloat16 hr=__float2bfloat16(v.x);
                __nv_bfloat16 hi=__float2bfloat16(v.y);
                sX[CG_XRH/2+fi*40+d]=hr;
                sX[CG_XRL/2+fi*40+d]=__float2bfloat16(v.x-__bfloat162float(hr));
                sX[CG_XIH/2+fi*40+d]=hi;
                sX[CG_XIL/2+fi*40+d]=__float2bfloat16(v.y-__bfloat162float(hi));
            }
        }
#pragma unroll
        for(int m=0;m<4;++m){
#pragma unroll
            for(int j=0;j<2;++j){
                int idx=tid+j*256;
                int row=idx>>2, part=idx&3;
                uint4 val=*reinterpret_cast<const uint4*>(gW[m]+(size_t)(c0+row)*CC+k0+part*8);
                *reinterpret_cast<uint4*>(smc+CG_W+m*10240+(row*40+part*8)*2)=val;
                if(m>=2){
                    uint4 nv=val;
                    nv.x^=0x80008000u; nv.y^=0x80008000u; nv.z^=0x80008000u; nv.w^=0x80008000u;
                    *reinterpret_cast<uint4*>(smc+CG_W+(m+2)*10240+(row*40+part*8)*2)=nv;
                }
            }
        }
        __syncthreads();
#pragma unroll
        for(int k16=0;k16<2;++k16){
            uint32_t xrh[2][4],xrl[2][4],xih[2][4],xil[2][4];
#pragma unroll
            for(int mb=0;mb<2;++mb){
                uint32_t off=(uint32_t)(((warp_m*32+mb*16+(lane&15))*40+(lane>>4)*8+k16*16)*2);
                LDM4(xrh[mb],uX+CG_XRH+off);
                LDM4(xrl[mb],uX+CG_XRL+off);
                LDM4(xih[mb],uX+CG_XIH+off);
                LDM4(xil[mb],uX+CG_XIL+off);
            }
#pragma unroll
            for(int ng=0;ng<2;++ng){
                uint32_t wrh[4],wrl[4],wih[4],wil[4],wnh[4],wnl[4];
                uint32_t off=(uint32_t)(((warp_n*32+ng*16+(lane&15))*40+(lane>>4)*8+k16*16)*2);
                LDM4(wrh,uX+CG_W+0*10240+off);
                LDM4(wrl,uX+CG_W+1*10240+off);
                LDM4(wih,uX+CG_W+2*10240+off);
                LDM4(wil,uX+CG_W+3*10240+off);
                LDM4(wnh,uX+CG_W+4*10240+off);
                LDM4(wnl,uX+CG_W+5*10240+off);
#pragma unroll
                for(int mb=0;mb<2;++mb){
#pragma unroll
                    for(int sub=0;sub<2;++sub){
                        float* dR=accR[mb][ng*2+sub];
                        float* dI=accI[mb][ng*2+sub];
                        MMA16816(dR,xrh[mb],wrh[sub],wrh[sub+2]);
                        MMA16816(dR,xrh[mb],wrl[sub],wrl[sub+2]);
                        MMA16816(dR,xrl[mb],wrh[sub],wrh[sub+2]);
                        MMA16816(dR,xih[mb],wnh[sub],wnh[sub+2]);
                        MMA16816(dR,xih[mb],wnl[sub],wnl[sub+2]);
                        MMA16816(dR,xil[mb],wnh[sub],wnh[sub+2]);
                        MMA16816(dI,xih[mb],wrh[sub],wrh[sub+2]);
                        MMA16816(dI,xih[mb],wrl[sub],wrl[sub+2]);
                        MMA16816(dI,xil[mb],wrh[sub],wrh[sub+2]);
                        MMA16816(dI,xrh[mb],wih[sub],wih[sub+2]);
                        MMA16816(dI,xrh[mb],wil[sub],wil[sub+2]);
                        MMA16816(dI,xrl[mb],wih[sub],wih[sub+2]);
                    }
                }
            }
        }
        __syncthreads();
    }
    float2* sO=(float2*)smc;
#pragma unroll
    for(int mb=0;mb<2;++mb){
#pragma unroll
        for(int half=0;half<2;++half){
            int f=warp_m*32+mb*16+half*8+(lane>>2);
#pragma unroll
            for(int nf=0;nf<4;++nf){
                int c=warp_n*32+nf*8+2*(lane&3);
                sO[(size_t)c*66+f]    =make_float2(accR[mb][nf][half*2+0],accI[mb][nf][half*2+0]);
                sO[(size_t)(c+1)*66+f]=make_float2(accR[mb][nf][half*2+1],accI[mb][nf][half*2+1]);
            }
        }
    }
    __syncthreads();
    for(int it=0;it<32;++it){
        int idx=tid+it*256;
        int c=idx>>6, f=idx&63;
        if(f0+f<NC)
            g_Xmap[((size_t)(b*CC+c0+c))*FF+f0+f]=sO[(size_t)c*66+f];
    }
}

/* fused-spectrum value at (hf,wf) for the channel pair */
__device__ __forceinline__ void fuse_pair(int hf,int wf,int kxi,int kyi,
        const float2* __restrict__ Xf0,const float2* __restrict__ Xf1,
        const float2* __restrict__ Xm0,const float2* __restrict__ Xm1,
        const float* al0,const float* al1,float2&v0,float2&v1){
    int fidx=hf*WF+wf;
    int bd=g_bid[fidx];
    if(hf<kxi && wf<kyi){
        int ci=hf*kyi+wf;
        float a0=al0[bd], a1=al1[bd];
        float2 m0=Xm0[ci], m1=Xm1[ci];
        v0=make_float2(a0*m0.x,a0*m0.y);
        v1=make_float2(a1*m1.x,a1*m1.y);
    } else {
        float b0=1.0f-al0[bd], b1=1.0f-al1[bd];
        float2 q0=Xf0[fidx], q1=Xf1[fidx];
        v0=make_float2(b0*q0.x,b0*q0.y);
        v1=make_float2(b1*q1.x,b1*q1.y);
    }
}

/* -------- inverse: packed fuse + complex IFFT2 of (c, c+1) + depthwise conv -------- */
__global__ void __launch_bounds__(512) k_fft_inv(const float* __restrict__ convw,
                                                 const float* __restrict__ kxp,const float* __restrict__ kyp){
    extern __shared__ __align__(16) float2 sm[];
    float2* S=sm; float2* tw=sm+128*SP;
    __shared__ float al0[NB], al1[NB], cw0[9], cw1[9];
    int tid=threadIdx.x;
    int bc0=blockIdx.x*2;
    int c0=bc0&(CC-1);
    if(tid<64){float s,cc;sincospif((float)tid/64.0f,&s,&cc);tw[tid]=make_float2(cc,s);}
    if(tid<NB)  al0[tid]=g_alpha[bc0*NB+tid];
    if(tid>=32&&tid<32+NB) al1[tid-32]=g_alpha[(bc0+1)*NB+(tid-32)];
    if(tid>=64&&tid<73)  cw0[tid-64]=convw[c0*9+(tid-64)];
    if(tid>=96&&tid<105) cw1[tid-96]=convw[(c0+1)*9+(tid-96)];
    int kxi=(int)floorf(sigm(kxp[0])*128.0f);
    int kyi=(int)floorf(sigm(kyp[0])*65.0f);
    __syncthreads();
    const float2* Xf0=g_Xf+(size_t)bc0*FF;   const float2* Xf1=Xf0+FF;
    const float2* Xm0=g_Xmap+(size_t)bc0*FF; const float2* Xm1=Xm0+FF;
    for(int idx=tid;idx<HWX;idx+=512){
        int h=idx>>7, w=idx&127;
        float2 v0,v1;
        if(w<=64){
            fuse_pair(h,w,kxi,kyi,Xf0,Xf1,Xm0,Xm1,al0,al1,v0,v1);
            if(w==0||w==64){
                float2 u0,u1;
                fuse_pair((128-h)&127,w,kxi,kyi,Xf0,Xf1,Xm0,Xm1,al0,al1,u0,u1);
                v0=make_float2((v0.x+u0.x)*0.5f,(v0.y-u0.y)*0.5f);
                v1=make_float2((v1.x+u1.x)*0.5f,(v1.y-u1.y)*0.5f);
            }
        } else {
            fuse_pair((128-h)&127,128-w,kxi,kyi,Xf0,Xf1,Xm0,Xm1,al0,al1,v0,v1);
            v0.y=-v0.y; v1.y=-v1.y;
        }
        S[h*SP+brev7(w)]=make_float2(v0.x-v1.y, v0.y+v1.x);
    }
    __syncthreads();
    for(int s=0;s<6;s+=3){
        int half=1<<s;
        for(int q=tid;q<2048;q+=512){
            int row=q&127, c=q>>7;
            int j=c&(half-1), g=c>>s;
            dit8(S,tw,row*SP+g*(half<<3)+j,half,j,s);
        }
        __syncthreads();
    }
    for(int q=tid;q<8192;q+=512){
        int row=q&127, j=q>>7;
        int i0=row*SP+j, i1=i0+64;
        float2 wv=tw[j];
        float2 u=S[i0], v=cmul(wv,S[i1]);
        S[i0]=cadd(u,v); S[i1]=csub(u,v);
    }
    __syncthreads();
    for(int stp=6;stp>=3;stp-=3){
        int hs=1<<(stp-2);
        for(int q=tid;q<2048;q+=512){
            int col=q&127, c=q>>7;
            int j=c&(hs-1), g=c>>(stp-2);
            dif8(S,tw,(g*(hs<<3)+j)*SP+col,SP,j,hs,stp);
        }
        __syncthreads();
    }
    for(int q=tid;q<8192;q+=512){
        int col=q&127, g=q>>7;
        int i0=(2*g)*SP+col, i1=i0+SP;
        float2 u=S[i0], v=S[i1];
        S[i0]=cadd(u,v); S[i1]=csub(u,v);
    }
    __syncthreads();
    const float* xp0=g_xt+(size_t)bc0*HWX;
    const float* xp1=xp0+HWX;
    float* yo0=g_yspec+(size_t)bc0*HWX;
    float* yo1=yo0+HWX;
    const float scale=1.0f/128.0f;
    for(int q=tid;q<4096;q+=512){
        int h=q>>5, w0=(q&31)*4;
        int hb=brev7(h);
        float2 z0=S[hb*SP+w0],   z1=S[hb*SP+w0+1];
        float2 z2=S[hb*SP+w0+2], z3=S[hb*SP+w0+3];
        float a0=z0.x*scale, a1=z1.x*scale, a2=z2.x*scale, a3=z3.x*scale;
        float e0=z0.y*scale, e1=z1.y*scale, e2=z2.y*scale, e3=z3.y*scale;
#pragma unroll
        for(int dy=-1;dy<=1;++dy){
            int hh=h+dy;
            if((unsigned)hh<128u){
                const float* rp0=xp0+hh*128+w0;
                const float* rp1=xp1+hh*128+w0;
                float l0=(w0>0)?rp0[-1]:0.0f, r0=(w0<124)?rp0[4]:0.0f;
                float l1=(w0>0)?rp1[-1]:0.0f, r1=(w0<124)?rp1[4]:0.0f;
                float4 m0=*reinterpret_cast<const float4*>(rp0);
                float4 m1=*reinterpret_cast<const float4*>(rp1);
                float c00=cw0[(dy+1)*3+0], c01=cw0[(dy+1)*3+1], c02=cw0[(dy+1)*3+2];
                float c10=cw1[(dy+1)*3+0], c11=cw1[(dy+1)*3+1], c12=cw1[(dy+1)*3+2];
                a0=fmaf(c00,l0,  fmaf(c01,m0.x,fmaf(c02,m0.y,a0)));
                a1=fmaf(c00,m0.x,fmaf(c01,m0.y,fmaf(c02,m0.z,a1)));
                a2=fmaf(c00,m0.y,fmaf(c01,m0.z,fmaf(c02,m0.w,a2)));
                a3=fmaf(c00,m0.z,fmaf(c01,m0.w,fmaf(c02,r0,  a3)));
                e0=fmaf(c10,l1,  fmaf(c11,m1.x,fmaf(c12,m1.y,e0)));
                e1=fmaf(c10,m1.x,fmaf(c11,m1.y,fmaf(c12,m1.z,e1)));
                e2=fmaf(c10,m1.y,fmaf(c11,m1.z,fmaf(c12,m1.w,e2)));
                e3=fmaf(c10,m1.z,fmaf(c11,m1.w,fmaf(c12,r1,  e3)));
            }
        }
        *reinterpret_cast<float4*>(yo0+h*128+w0)=make_float4(a0,a1,a2,a3);
        *reinterpret_cast<float4*>(yo1+h*128+w0)=make_float4(e0,e1,e2,e3);
    }
}

/* ---------------- HMMA pointwise GEMM (cp.async double-buffered) + yspec + LN ---------------- */
#define PB_AH 0
#define PB_AL 10240
#define PB_BH 20480
#define PB_BL 40960
#define PB_SZ 61440
#define FS_AUX 122880
#define FS_SUM (FS_AUX+0)
#define FS_SQ  (FS_AUX+2048)
#define FS_MR  (FS_AUX+4096)
#define FS_LB  (FS_AUX+5120)
#define FS_WGT (FS_AUX+6144)
#define FS_BSH (FS_AUX+7168)
#define FIN_SMEM (FS_AUX+8192)
#define ASTR 40

__global__ void __launch_bounds__(512,1) k_final_hmma(
        const float* __restrict__ linb, const float* __restrict__ timev,
        const float* __restrict__ nww, const float* __restrict__ nwb,
        const float* __restrict__ nbw, const float* __restrict__ nbb,
        float* __restrict__ out){
    extern __shared__ __align__(16) char smem[];
    float* s_sum=(float*)(smem+FS_SUM);
    float* s_sq =(float*)(smem+FS_SQ);
    float* s_mr =(float*)(smem+FS_MR);
    float* s_lb =(float*)(smem+FS_LB);
    float* s_wgt=(float*)(smem+FS_WGT);
    float* s_bsh=(float*)(smem+FS_BSH);
    uint32_t uS=smem_u32(smem);

    int tid=threadIdx.x, lane=tid&31, wid=tid>>5;
    int warp_m=wid&3, warp_n=wid>>2;
    int b=blockIdx.y, p0=blockIdx.x*128;
    float tv=timev[b];
    for(int c=tid;c<CC;c+=512){
        s_lb[c]=linb[c];
        s_wgt[c]=tv*nww[c]+nwb[c];
        s_bsh[c]=tv*nbw[c]+nbb[c];
    }
    float acc[2][8][4];
#pragma unroll
    for(int i=0;i<2;++i)
#pragma unroll
        for(int j=0;j<8;++j)
#pragma unroll
            for(int k=0;k<4;++k) acc[i][j][k]=0.0f;

    const __nv_bfloat16* xh=g_xhi+((size_t)b*HWX+p0)*CC;
    const __nv_bfloat16* xl=g_xlo+((size_t)b*HWX+p0)*CC;
    int r=tid>>2, part=tid&3;
    uint32_t soff=(uint32_t)((r*ASTR+part*8)*2);
    size_t goffA=(size_t)r*CC+part*8;

    auto issue=[&](int kc){
        uint32_t base=(kc&1)*PB_SZ;
        CPA16(uS+base+PB_AH+soff, xh+goffA+kc*32);
        CPA16(uS+base+PB_AL+soff, xl+goffA+kc*32);
#pragma unroll
        for(int i=0;i<2;++i){
            int n=r+i*128;
            uint32_t so2=(uint32_t)((n*ASTR+part*8)*2);
            CPA16(uS+base+PB_BH+so2, g_whi+(size_t)n*CC+kc*32+part*8);
            CPA16(uS+base+PB_BL+so2, g_wlo+(size_t)n*CC+kc*32+part*8);
        }
        CPA_COMMIT();
    };
    issue(0);
    for(int kc=0;kc<8;++kc){
        if(kc<7){ issue(kc+1); CPA_WAIT(1); }
        else CPA_WAIT(0);
        __syncthreads();
        uint32_t base=(kc&1)*PB_SZ;
#pragma unroll
        for(int k16=0;k16<2;++k16){
            uint32_t ah[2][4], al[2][4];
#pragma unroll
            for(int mb=0;mb<2;++mb){
                uint32_t off=(uint32_t)(((warp_m*32+mb*16+(lane&15))*ASTR + (lane>>4)*8 + k16*16)*2);
                LDM4(ah[mb],uS+base+PB_AH+off);
                LDM4(al[mb],uS+base+PB_AL+off);
            }
#pragma unroll
            for(int nb=0;nb<4;++nb){
                uint32_t bh[4], bl[4];
                uint32_t off=(uint32_t)(((warp_n*64+nb*16+(lane&15))*ASTR + (lane>>4)*8 + k16*16)*2);
                LDM4(bh,uS+base+PB_BH+off);
                LDM4(bl,uS+base+PB_BL+off);
#pragma unroll
                for(int mb=0;mb<2;++mb){
#pragma unroll
                    for(int sub=0;sub<2;++sub){
                        float* d=acc[mb][nb*2+sub];
                        MMA16816(d,ah[mb],bh[sub],bh[sub+2]);
                        MMA16816(d,ah[mb],bl[sub],bl[sub+2]);
                        MMA16816(d,al[mb],bh[sub],bh[sub+2]);
                    }
                }
            }
        }
        __syncthreads();
    }
    const float* yb=g_yst+((size_t)b*HWX+p0)*CC;
#pragma unroll
    for(int mb=0;mb<2;++mb){
#pragma unroll
        for(int half=0;half<2;++half){
            int row=warp_m*32+mb*16+half*8+(lane>>2);
            float rs=0.0f, rq=0.0f;
#pragma unroll
            for(int nf=0;nf<8;++nf){
                int c=warp_n*64+nf*8+2*(lane&3);
                float2 yv=*reinterpret_cast<const float2*>(yb+(size_t)row*CC+c);
                float v0=acc[mb][nf][half*2+0]+s_lb[c]  +yv.x;
                float v1=acc[mb][nf][half*2+1]+s_lb[c+1]+yv.y;
                acc[mb][nf][half*2+0]=v0;
                acc[mb][nf][half*2+1]=v1;
                rs+=v0+v1; rq+=v0*v0+v1*v1;
            }
            rs+=__shfl_xor_sync(0xffffffffu,rs,1);
            rs+=__shfl_xor_sync(0xffffffffu,rs,2);
            rq+=__shfl_xor_sync(0xffffffffu,rq,1);
            rq+=__shfl_xor_sync(0xffffffffu,rq,2);
            if((lane&3)==0){
                s_sum[warp_n*128+row]=rs;
                s_sq [warp_n*128+row]=rq;
            }
        }
    }
    __syncthreads();
    if(tid<128){
        float s=0.0f,q=0.0f;
#pragma unroll
        for(int w=0;w<4;++w){ s+=s_sum[w*128+tid]; q+=s_sq[w*128+tid]; }
        float mean=s*(1.0f/256.0f);
        float var=q*(1.0f/256.0f)-mean*mean;
        s_mr[tid]=mean;
        s_mr[128+tid]=rsqrtf(var+1e-5f);
    }
    __syncthreads();
#pragma unroll
    for(int mb=0;mb<2;++mb){
#pragma unroll
        for(int half=0;half<2;++half){
            int row=warp_m*32+mb*16+half*8+(lane>>2);
            float mn=s_mr[row], rst=s_mr[128+row];
            size_t base=((size_t)b*HWX+p0+row)*CC;
#pragma unroll
            for(int nf=0;nf<8;++nf){
                int c=warp_n*64+nf*8+2*(lane&3);
                float2 o;
                o.x=s_wgt[c]  *((acc[mb][nf][half*2+0]-mn)*rst)+s_bsh[c];
                o.y=s_wgt[c+1]*((acc[mb][nf][half*2+1]-mn)*rst)+s_bsh[c+1];
                *reinterpret_cast<float2*>(out+base+c)=o;
            }
        }
    }
}

extern "C" void kernel_launch(void* const* d_in, const int* in_sizes, int n_in,
                              void* d_out, int out_size){
    const float* x      =(const float*)d_in[0];
    const float* timev  =(const float*)d_in[1];
    const float* w_real =(const float*)d_in[2];
    const float* w_imag =(const float*)d_in[3];
    const float* conv_w =(const float*)d_in[4];
    const float* lin_w  =(const float*)d_in[5];
    const float* lin_b  =(const float*)d_in[6];
    const float* mlp_w1 =(const float*)d_in[7];
    const float* mlp_b1 =(const float*)d_in[8];
    const float* mlp_w2 =(const float*)d_in[9];
    const float* mlp_b2 =(const float*)d_in[10];
    const float* norm_ww=(const float*)d_in[11];
    const float* norm_wb=(const float*)d_in[12];
    const float* norm_bw=(const float*)d_in[13];
    const float* norm_bb=(const float*)d_in[14];
    const float* kx     =(const float*)d_in[15];
    const float* ky     =(const float*)d_in[16];
    float* out=(float*)d_out;

    const int FFT_SMEM=(128*SP+64)*sizeof(float2);
    cudaFuncSetAttribute(k_fft_fwd,cudaFuncAttributeMaxDynamicSharedMemorySize,FFT_SMEM);
    cudaFuncSetAttribute(k_fft_inv,cudaFuncAttributeMaxDynamicSharedMemorySize,FFT_SMEM);
    cudaFuncSetAttribute(k_final_hmma,cudaFuncAttributeMaxDynamicSharedMemorySize,FIN_SMEM);
    cudaFuncSetAttribute(k_cgemm_hmma,cudaFuncAttributeMaxDynamicSharedMemorySize,CG_SMEM);

    k_init<<<1,1024>>>();
    {
        dim3 g(HWX/32,CC/32,BB), blk(32,8);
        k_transpose<<<g,blk>>>(x);
    }
    k_split3<<<(3*CC*CC+255)/256,256>>>(lin_w,w_real,w_imag);
    k_fft_fwd<<<BB*CC/2,512,FFT_SMEM>>>(mlp_w1,mlp_b1,mlp_w2,mlp_b2);
    {
        dim3 g((FF+63)/64,CC/128,BB);
        k_cgemm_hmma<<<g,256,CG_SMEM>>>(kx,ky);
    }
    k_fft_inv<<<BB*CC/2,512,FFT_SMEM>>>(conv_w,kx,ky);
    {
        dim3 g(HWX/32,CC/32,BB), blk(32,8);
        k_transb<<<g,blk>>>();
    }
    {
        dim3 g(HWX/128,BB);
        k_final_hmma<<<g,512,FIN_SMEM>>>(lin_b,timev,norm_ww,norm_wb,norm_bw,norm_bb,out);
    }
}

// round 15
// speedup vs baseline: 1.1576x; 1.1576x over previous
#include <cuda_runtime.h>
#include <cuda_bf16.h>
#include <math.h>
#include <stdint.h>

#define BB 4
#define CC 256
#define HWX 16384
#define HF 128
#define WF 65
#define FF (HF*WF)
#define NB 6
#define GH 128
#define SP 129

typedef unsigned long long ull;

__device__ float  g_xt[(size_t)BB*CC*HWX];
__device__ float2 g_Xf[(size_t)BB*CC*FF];
__device__ float2 g_Xmap[(size_t)BB*CC*FF];
__device__ float  g_yspec[(size_t)BB*CC*HWX];
__device__ __nv_bfloat16 g_xhi[(size_t)BB*CC*HWX];
__device__ __nv_bfloat16 g_xlo[(size_t)BB*CC*HWX];
__device__ __nv_bfloat16 g_whi[CC*CC];
__device__ __nv_bfloat16 g_wlo[CC*CC];
__device__ __nv_bfloat16 g_wrh[CC*CC];
__device__ __nv_bfloat16 g_wrl[CC*CC];
__device__ __nv_bfloat16 g_wih[CC*CC];
__device__ __nv_bfloat16 g_wil[CC*CC];
__device__ float  g_alpha[BB*CC*NB];
__device__ int    g_bid[FF];
__device__ float  g_cnt[NB];

__device__ __forceinline__ float2 cmul(float2 a, float2 b){return make_float2(a.x*b.x-a.y*b.y,a.x*b.y+a.y*b.x);}
__device__ __forceinline__ float2 cadd(float2 a, float2 b){return make_float2(a.x+b.x,a.y+b.y);}
__device__ __forceinline__ float2 csub(float2 a, float2 b){return make_float2(a.x-b.x,a.y-b.y);}
__device__ __forceinline__ int brev7(int x){return (int)(__brev((unsigned)x)>>25);}
__device__ __forceinline__ float sigm(float x){return 1.0f/(1.0f+expf(-x));}

__device__ __forceinline__ uint32_t smem_u32(const void* p){
    uint32_t a;asm("{ .reg .u64 t; cvta.to.shared.u64 t, %1; cvt.u32.u64 %0, t; }":"=r"(a):"l"(p));return a;
}
#define LDM4(d,adr) asm volatile("ldmatrix.sync.aligned.m8n8.x4.shared.b16 {%0,%1,%2,%3},[%4];" \
    :"=r"((d)[0]),"=r"((d)[1]),"=r"((d)[2]),"=r"((d)[3]):"r"(adr))
#define MMA16816(d,a,b0,b1) asm volatile( \
    "mma.sync.aligned.m16n8k16.row.col.f32.bf16.bf16.f32 {%0,%1,%2,%3},{%4,%5,%6,%7},{%8,%9},{%0,%1,%2,%3};" \
    : "+f"((d)[0]),"+f"((d)[1]),"+f"((d)[2]),"+f"((d)[3]) \
    : "r"((a)[0]),"r"((a)[1]),"r"((a)[2]),"r"((a)[3]),"r"(b0),"r"(b1))
#define CPA16(dst,src) asm volatile("cp.async.cg.shared.global [%0],[%1],16;"::"r"(dst),"l"(src))
#define CPA_COMMIT()   asm volatile("cp.async.commit_group;":::"memory")
#define CPA_WAIT(n)    asm volatile("cp.async.wait_group %0;"::"n"(n):"memory")

/* band table: bit-exact float32 replica of the numpy band partition */
__global__ void k_init(){
    __shared__ int cnt[NB];
    int tid=threadIdx.x;
    if(tid<NB) cnt[tid]=0;
    __syncthreads();
    const float rmax=__fsqrt_rn(2.0f);
    for(int f=tid;f<FF;f+=blockDim.x){
        int h=f/WF, w=f-(f/WF)*WF;
        float a=__fdiv_rn((float)h,127.0f);
        float b=__fdiv_rn((float)w,64.0f);
        float s=__fadd_rn(__fmul_rn(a,a),__fmul_rn(b,b));
        float r=__fsqrt_rn(s);
        float rn=__fdiv_rn(r,rmax);
        int bd=(int)floorf(__fmul_rn(rn,6.0f));
        if(bd>NB-1) bd=NB-1;
        g_bid[f]=bd;
        atomicAdd(&cnt[bd],1);
    }
    __syncthreads();
    if(tid<NB) g_cnt[tid]=(float)max(cnt[tid],1);
}

/* (B,HW,C) -> (B,C,HW), fused bf16 hi/lo split kept in (B,HW,C) */
__global__ void k_transpose(const float* __restrict__ x){
    __shared__ float t[32][33];
    int b=blockIdx.z, p0=blockIdx.x*32, c0=blockIdx.y*32;
    int tx=threadIdx.x, ty=threadIdx.y;
#pragma unroll
    for(int i=0;i<32;i+=8){
        size_t idx=((size_t)b*HWX+(p0+ty+i))*CC+c0+tx;
        float v=x[idx];
        t[ty+i][tx]=v;
        __nv_bfloat16 h=__float2bfloat16(v);
        g_xhi[idx]=h;
        g_xlo[idx]=__float2bfloat16(v-__bfloat162float(h));
    }
    __syncthreads();
#pragma unroll
    for(int i=0;i<32;i+=8) g_xt[((size_t)b*CC+(c0+ty+i))*HWX+p0+tx]=t[tx][ty+i];
}

/* split all three weight matrices in one launch */
__global__ void k_split3(const float* __restrict__ w0,const float* __restrict__ w1,const float* __restrict__ w2){
    int i=blockIdx.x*blockDim.x+threadIdx.x;
    int m=i>>16, r=i&65535;
    if(m>2) return;
    const float* src=(m==0)?w0:(m==1)?w1:w2;
    __nv_bfloat16* hi=(m==0)?g_whi:(m==1)?g_wrh:g_wih;
    __nv_bfloat16* lo=(m==0)?g_wlo:(m==1)?g_wrl:g_wil;
    float v=src[r];
    __nv_bfloat16 h=__float2bfloat16(v);
    hi[r]=h;
    lo[r]=__float2bfloat16(v-__bfloat162float(h));
}

/* ---- radix-8 triple-stage butterflies (DIT rows / DIF cols) ---- */
__device__ __forceinline__ void dit8(float2* S,const float2* tw,int base,int half,int j,int s){
    float2 x0=S[base],x1=S[base+half],x2=S[base+2*half],x3=S[base+3*half];
    float2 x4=S[base+4*half],x5=S[base+5*half],x6=S[base+6*half],x7=S[base+7*half];
    float2 w1=tw[j<<(6-s)];
    float2 t1=cmul(w1,x1),t3=cmul(w1,x3),t5=cmul(w1,x5),t7=cmul(w1,x7);
    float2 a0=cadd(x0,t1),a1=csub(x0,t1),a2=cadd(x2,t3),a3=csub(x2,t3);
    float2 a4=cadd(x4,t5),a5=csub(x4,t5),a6=cadd(x6,t7),a7=csub(x6,t7);
    float2 w2a=tw[j<<(5-s)],w2b=tw[(j+half)<<(5-s)];
    float2 u2=cmul(w2a,a2),u3=cmul(w2b,a3),u6=cmul(w2a,a6),u7=cmul(w2b,a7);
    float2 b0=cadd(a0,u2),b2=csub(a0,u2),b1=cadd(a1,u3),b3=csub(a1,u3);
    float2 b4=cadd(a4,u6),b6=csub(a4,u6),b5=cadd(a5,u7),b7=csub(a5,u7);
    float2 w30=tw[j<<(4-s)],w31=tw[(j+half)<<(4-s)],w32=tw[(j+2*half)<<(4-s)],w33=tw[(j+3*half)<<(4-s)];
    float2 v4=cmul(w30,b4),v5=cmul(w31,b5),v6=cmul(w32,b6),v7=cmul(w33,b7);
    S[base]=cadd(b0,v4);        S[base+4*half]=csub(b0,v4);
    S[base+half]=cadd(b1,v5);   S[base+5*half]=csub(b1,v5);
    S[base+2*half]=cadd(b2,v6); S[base+6*half]=csub(b2,v6);
    S[base+3*half]=cadd(b3,v7); S[base+7*half]=csub(b3,v7);
}
__device__ __forceinline__ void dif8(float2* S,const float2* tw,int i0,int strd,int j,int hs,int stp){
    float2 x0=S[i0],x1=S[i0+hs*strd],x2=S[i0+2*hs*strd],x3=S[i0+3*hs*strd];
    float2 x4=S[i0+4*hs*strd],x5=S[i0+5*hs*strd],x6=S[i0+6*hs*strd],x7=S[i0+7*hs*strd];
    float2 a0=cadd(x0,x4), a4=cmul(tw[(j     )<<(6-stp)],csub(x0,x4));
    float2 a1=cadd(x1,x5), a5=cmul(tw[(j+hs  )<<(6-stp)],csub(x1,x5));
    float2 a2=cadd(x2,x6), a6=cmul(tw[(j+2*hs)<<(6-stp)],csub(x2,x6));
    float2 a3=cadd(x3,x7), a7=cmul(tw[(j+3*hs)<<(6-stp)],csub(x3,x7));
    float2 wb0=tw[j<<(7-stp)], wb1=tw[(j+hs)<<(7-stp)];
    float2 b0=cadd(a0,a2), b2=cmul(wb0,csub(a0,a2));
    float2 b1=cadd(a1,a3), b3=cmul(wb1,csub(a1,a3));
    float2 b4=cadd(a4,a6), b6=cmul(wb0,csub(a4,a6));
    float2 b5=cadd(a5,a7), b7=cmul(wb1,csub(a5,a7));
    float2 wc=tw[j<<(8-stp)];
    S[i0]=cadd(b0,b1);           S[i0+hs*strd]=cmul(wc,csub(b0,b1));
    S[i0+2*hs*strd]=cadd(b2,b3); S[i0+3*hs*strd]=cmul(wc,csub(b2,b3));
    S[i0+4*hs*strd]=cadd(b4,b5); S[i0+5*hs*strd]=cmul(wc,csub(b4,b5));
    S[i0+6*hs*strd]=cadd(b6,b7); S[i0+7*hs*strd]=cmul(wc,csub(b6,b7));
}

/* -------- forward (512 thr): packed complex FFT2 + band sums + fused gate MLP -------- */
__global__ void __launch_bounds__(512) k_fft_fwd(const float* __restrict__ mw1,const float* __restrict__ mb1,
                                                  const float* __restrict__ mw2,const float* __restrict__ mb2){
    extern __shared__ __align__(16) float2 sm[];
    float2* S=sm; float2* tw=sm+128*SP;
    __shared__ float wsum[16][2*NB];
    __shared__ float means[2*NB], hb[2*GH];
    int tid=threadIdx.x;
    int lane=tid&31, wid=tid>>5;
    int bc0=blockIdx.x*2;
    const float* x0=g_xt+(size_t)bc0*HWX;
    const float* x1=x0+HWX;
    if(tid<64){float s,c;sincospif(-(float)tid/64.0f,&s,&c);tw[tid]=make_float2(c,s);}
    for(int idx=tid;idx<HWX;idx+=512){
        int h=idx>>7, w=idx&127;
        S[h*SP+brev7(w)]=make_float2(x0[idx],x1[idx]);
    }
    __syncthreads();
    for(int s=0;s<6;s+=3){
        int half=1<<s;
        for(int q=tid;q<2048;q+=512){
            int row=q&127, c=q>>7;
            int j=c&(half-1), g=c>>s;
            dit8(S,tw,row*SP+g*(half<<3)+j,half,j,s);
        }
        __syncthreads();
    }
    for(int q=tid;q<8192;q+=512){
        int row=q&127, j=q>>7;
        int i0=row*SP+j, i1=i0+64;
        float2 wv=tw[j];
        float2 u=S[i0], v=cmul(wv,S[i1]);
        S[i0]=cadd(u,v); S[i1]=csub(u,v);
    }
    __syncthreads();
    for(int stp=6;stp>=3;stp-=3){
        int hs=1<<(stp-2);
        for(int q=tid;q<2048;q+=512){
            int col=q&127, c=q>>7;
            int j=c&(hs-1), g=c>>(stp-2);
            dif8(S,tw,(g*(hs<<3)+j)*SP+col,SP,j,hs,stp);
        }
        __syncthreads();
    }
    for(int q=tid;q<8192;q+=512){
        int col=q&127, g=q>>7;
        int i0=(2*g)*SP+col, i1=i0+SP;
        float2 u=S[i0], v=S[i1];
        S[i0]=cadd(u,v); S[i1]=csub(u,v);
    }
    __syncthreads();
    float acc[2*NB];
#pragma unroll
    for(int k=0;k<2*NB;++k) acc[k]=0.0f;
    const float hs2=0.5f/128.0f;
    float2* Xo0=g_Xf+(size_t)bc0*FF;
    float2* Xo1=Xo0+FF;
    for(int idx=tid;idx<FF;idx+=512){
        int hf=idx/WF, w=idx-hf*WF;
        float2 Z1=S[brev7(hf)*SP+w];
        int h2=(128-hf)&127, w2=(128-w)&127;
        float2 Z2=S[brev7(h2)*SP+w2];
        float2 v0=make_float2((Z1.x+Z2.x)*hs2,(Z1.y-Z2.y)*hs2);
        float2 v1=make_float2((Z1.y+Z2.y)*hs2,(Z2.x-Z1.x)*hs2);
        Xo0[idx]=v0; Xo1[idx]=v1;
        float m0=sqrtf(v0.x*v0.x+v0.y*v0.y);
        float m1=sqrtf(v1.x*v1.x+v1.y*v1.y);
        int bd=g_bid[idx];
#pragma unroll
        for(int k=0;k<NB;++k){
            acc[k]   +=(bd==k)?m0:0.0f;
            acc[NB+k]+=(bd==k)?m1:0.0f;
        }
    }
#pragma unroll
    for(int k=0;k<2*NB;++k){
        float v=acc[k];
#pragma unroll
        for(int o=16;o;o>>=1) v+=__shfl_xor_sync(0xffffffffu,v,o);
        if(lane==0) wsum[wid][k]=v;
    }
    __syncthreads();
    if(tid<2*NB){
        float s=0.0f;
#pragma unroll
        for(int w=0;w<16;++w) s+=wsum[w][tid];
        int k=tid%NB;
        means[tid]=s/(g_cnt[k]+1e-6f);
    }
    __syncthreads();
    if(tid<2*GH){
        int ch=tid>>7, hh=tid&127;
        float hv=mb1[hh];
#pragma unroll
        for(int n=0;n<NB;++n) hv+=mw1[hh*NB+n]*means[ch*NB+n];
        hb[tid]=fmaxf(hv,0.0f);
    }
    __syncthreads();
    if(wid<2*NB){
        int ch=wid/NB, n=wid-ch*NB;
        float v=0.0f;
#pragma unroll
        for(int i=0;i<4;++i){int hh=lane+32*i; v+=mw2[n*GH+hh]*hb[ch*GH+hh];}
#pragma unroll
        for(int o=16;o;o>>=1) v+=__shfl_xor_sync(0xffffffffu,v,o);
        if(lane==0) g_alpha[(bc0+ch)*NB+n]=1.0f/(1.0f+expf(-(v+mb2[n])));
    }
}

/* ---------------- HMMA complex GEMM on masked freqs ---------------- */
#define CG_XRH 0
#define CG_XRL 5120
#define CG_XIH 10240
#define CG_XIL 15360
#define CG_W   20480
#define CG_SMEM 81920

__global__ void __launch_bounds__(256) k_cgemm_hmma(const float* __restrict__ kxp,const float* __restrict__ kyp){
    extern __shared__ __align__(16) char smc[];
    int kxi=(int)floorf(sigm(kxp[0])*128.0f);
    int kyi=(int)floorf(sigm(kyp[0])*65.0f);
    int NC=kxi*kyi;
    int f0=blockIdx.x*64;
    if(f0>=NC) return;
    int c0=blockIdx.y*128, b=blockIdx.z;
    __shared__ int fmap[64];
    int tid=threadIdx.x, lane=tid&31, wid=tid>>5;
    int warp_m=wid&1, warp_n=wid>>1;
    if(tid<64){
        int f=f0+tid;
        fmap[tid]=(f<NC)?((f/kyi)*WF+(f-(f/kyi)*kyi)):-1;
    }
    __nv_bfloat16* sX=(__nv_bfloat16*)smc;
    uint32_t uX=smem_u32(smc);
    float accR[2][4][4], accI[2][4][4];
#pragma unroll
    for(int i=0;i<2;++i)
#pragma unroll
        for(int j=0;j<4;++j)
#pragma unroll
            for(int k=0;k<4;++k){accR[i][j][k]=0.0f;accI[i][j][k]=0.0f;}
    __syncthreads();

    const __nv_bfloat16* gW[4]={g_wrh,g_wrl,g_wih,g_wil};
    for(int kc=0;kc<8;++kc){
        int k0=kc*32;
        {
            int fi=tid&63, ds=tid>>6;
            int mp=fmap[fi];
#pragma unroll
            for(int i=0;i<8;++i){
                int d=ds*8+i;
                float2 v=make_float2(0.0f,0.0f);
                if(mp>=0) v=g_Xf[((size_t)(b*CC+k0+d))*FF+mp];
                __nv_bfloat16 hr=__float2bfloat16(v.x);
                __nv_bfloat16 hi=__float2bfloat16(v.y);
                sX[CG_XRH/2+fi*40+d]=hr;
                sX[CG_XRL/2+fi*40+d]=__float2bfloat16(v.x-__bfloat162float(hr));
                sX[CG_XIH/2+fi*40+d]=hi;
                sX[CG_XIL/2+fi*40+d]=__float2bfloat16(v.y-__bfloat162float(hi));
            }
        }
#pragma unroll
        for(int m=0;m<4;++m){
#pragma unroll
            for(int j=0;j<2;++j){
                int idx=tid+j*256;
                int row=idx>>2, part=idx&3;
                uint4 val=*reinterpret_cast<const uint4*>(gW[m]+(size_t)(c0+row)*CC+k0+part*8);
                *reinterpret_cast<uint4*>(smc+CG_W+m*10240+(row*40+part*8)*2)=val;
                if(m>=2){
                    uint4 nv=val;
                    nv.x^=0x80008000u; nv.y^=0x80008000u; nv.z^=0x80008000u; nv.w^=0x80008000u;
                    *reinterpret_cast<uint4*>(smc+CG_W+(m+2)*10240+(row*40+part*8)*2)=nv;
                }
            }
        }
        __syncthreads();
#pragma unroll
        for(int k16=0;k16<2;++k16){
            uint32_t xrh[2][4],xrl[2][4],xih[2][4],xil[2][4];
#pragma unroll
            for(int mb=0;mb<2;++mb){
                uint32_t off=(uint32_t)(((warp_m*32+mb*16+(lane&15))*40+(lane>>4)*8+k16*16)*2);
                LDM4(xrh[mb],uX+CG_XRH+off);
                LDM4(xrl[mb],uX+CG_XRL+off);
                LDM4(xih[mb],uX+CG_XIH+off);
                LDM4(xil[mb],uX+CG_XIL+off);
            }
#pragma unroll
            for(int ng=0;ng<2;++ng){
                uint32_t wrh[4],wrl[4],wih[4],wil[4],wnh[4],wnl[4];
                uint32_t off=(uint32_t)(((warp_n*32+ng*16+(lane&15))*40+(lane>>4)*8+k16*16)*2);
                LDM4(wrh,uX+CG_W+0*10240+off);
                LDM4(wrl,uX+CG_W+1*10240+off);
                LDM4(wih,uX+CG_W+2*10240+off);
                LDM4(wil,uX+CG_W+3*10240+off);
                LDM4(wnh,uX+CG_W+4*10240+off);
                LDM4(wnl,uX+CG_W+5*10240+off);
#pragma unroll
                for(int mb=0;mb<2;++mb){
#pragma unroll
                    for(int sub=0;sub<2;++sub){
                        float* dR=accR[mb][ng*2+sub];
                        float* dI=accI[mb][ng*2+sub];
                        MMA16816(dR,xrh[mb],wrh[sub],wrh[sub+2]);
                        MMA16816(dR,xrh[mb],wrl[sub],wrl[sub+2]);
                        MMA16816(dR,xrl[mb],wrh[sub],wrh[sub+2]);
                        MMA16816(dR,xih[mb],wnh[sub],wnh[sub+2]);
                        MMA16816(dR,xih[mb],wnl[sub],wnl[sub+2]);
                        MMA16816(dR,xil[mb],wnh[sub],wnh[sub+2]);
                        MMA16816(dI,xih[mb],wrh[sub],wrh[sub+2]);
                        MMA16816(dI,xih[mb],wrl[sub],wrl[sub+2]);
                        MMA16816(dI,xil[mb],wrh[sub],wrh[sub+2]);
                        MMA16816(dI,xrh[mb],wih[sub],wih[sub+2]);
                        MMA16816(dI,xrh[mb],wil[sub],wil[sub+2]);
                        MMA16816(dI,xrl[mb],wih[sub],wih[sub+2]);
                    }
                }
            }
        }
        __syncthreads();
    }
    float2* sO=(float2*)smc;
#pragma unroll
    for(int mb=0;mb<2;++mb){
#pragma unroll
        for(int half=0;half<2;++half){
            int f=warp_m*32+mb*16+half*8+(lane>>2);
#pragma unroll
            for(int nf=0;nf<4;++nf){
                int c=warp_n*32+nf*8+2*(lane&3);
                sO[(size_t)c*66+f]    =make_float2(accR[mb][nf][half*2+0],accI[mb][nf][half*2+0]);
                sO[(size_t)(c+1)*66+f]=make_float2(accR[mb][nf][half*2+1],accI[mb][nf][half*2+1]);
            }
        }
    }
    __syncthreads();
    for(int it=0;it<32;++it){
        int idx=tid+it*256;
        int c=idx>>6, f=idx&63;
        if(f0+f<NC)
            g_Xmap[((size_t)(b*CC+c0+c))*FF+f0+f]=sO[(size_t)c*66+f];
    }
}

/* fused-spectrum value at (hf,wf) for the channel pair */
__device__ __forceinline__ void fuse_pair(int hf,int wf,int kxi,int kyi,
        const float2* __restrict__ Xf0,const float2* __restrict__ Xf1,
        const float2* __restrict__ Xm0,const float2* __restrict__ Xm1,
        const float* al0,const float* al1,float2&v0,float2&v1){
    int fidx=hf*WF+wf;
    int bd=g_bid[fidx];
    if(hf<kxi && wf<kyi){
        int ci=hf*kyi+wf;
        float a0=al0[bd], a1=al1[bd];
        float2 m0=Xm0[ci], m1=Xm1[ci];
        v0=make_float2(a0*m0.x,a0*m0.y);
        v1=make_float2(a1*m1.x,a1*m1.y);
    } else {
        float b0=1.0f-al0[bd], b1=1.0f-al1[bd];
        float2 q0=Xf0[fidx], q1=Xf1[fidx];
        v0=make_float2(b0*q0.x,b0*q0.y);
        v1=make_float2(b1*q1.x,b1*q1.y);
    }
}

/* -------- inverse (1024 thr): packed fuse + complex IFFT2 + depthwise conv -------- */
__global__ void __launch_bounds__(1024) k_fft_inv(const float* __restrict__ convw,
                                                 const float* __restrict__ kxp,const float* __restrict__ kyp){
    extern __shared__ __align__(16) float2 sm[];
    float2* S=sm; float2* tw=sm+128*SP;
    __shared__ float al0[NB], al1[NB], cw0[9], cw1[9];
    int tid=threadIdx.x;
    int bc0=blockIdx.x*2;
    int c0=bc0&(CC-1);
    if(tid<64){float s,cc;sincospif((float)tid/64.0f,&s,&cc);tw[tid]=make_float2(cc,s);}
    if(tid<NB)  al0[tid]=g_alpha[bc0*NB+tid];
    if(tid>=32&&tid<32+NB) al1[tid-32]=g_alpha[(bc0+1)*NB+(tid-32)];
    if(tid>=64&&tid<73)  cw0[tid-64]=convw[c0*9+(tid-64)];
    if(tid>=96&&tid<105) cw1[tid-96]=convw[(c0+1)*9+(tid-96)];
    int kxi=(int)floorf(sigm(kxp[0])*128.0f);
    int kyi=(int)floorf(sigm(kyp[0])*65.0f);
    __syncthreads();
    const float2* Xf0=g_Xf+(size_t)bc0*FF;   const float2* Xf1=Xf0+FF;
    const float2* Xm0=g_Xmap+(size_t)bc0*FF; const float2* Xm1=Xm0+FF;
    for(int idx=tid;idx<HWX;idx+=1024){
        int h=idx>>7, w=idx&127;
        float2 v0,v1;
        if(w<=64){
            fuse_pair(h,w,kxi,kyi,Xf0,Xf1,Xm0,Xm1,al0,al1,v0,v1);
            if(w==0||w==64){
                float2 u0,u1;
                fuse_pair((128-h)&127,w,kxi,kyi,Xf0,Xf1,Xm0,Xm1,al0,al1,u0,u1);
                v0=make_float2((v0.x+u0.x)*0.5f,(v0.y-u0.y)*0.5f);
                v1=make_float2((v1.x+u1.x)*0.5f,(v1.y-u1.y)*0.5f);
            }
        } else {
            fuse_pair((128-h)&127,128-w,kxi,kyi,Xf0,Xf1,Xm0,Xm1,al0,al1,v0,v1);
            v0.y=-v0.y; v1.y=-v1.y;
        }
        S[h*SP+brev7(w)]=make_float2(v0.x-v1.y, v0.y+v1.x);
    }
    __syncthreads();
    for(int s=0;s<6;s+=3){
        int half=1<<s;
        for(int q=tid;q<2048;q+=1024){
            int row=q&127, c=q>>7;
            int j=c&(half-1), g=c>>s;
            dit8(S,tw,row*SP+g*(half<<3)+j,half,j,s);
        }
        __syncthreads();
    }
    for(int q=tid;q<8192;q+=1024){
        int row=q&127, j=q>>7;
        int i0=row*SP+j, i1=i0+64;
        float2 wv=tw[j];
        float2 u=S[i0], v=cmul(wv,S[i1]);
        S[i0]=cadd(u,v); S[i1]=csub(u,v);
    }
    __syncthreads();
    for(int stp=6;stp>=3;stp-=3){
        int hs=1<<(stp-2);
        for(int q=tid;q<2048;q+=1024){
            int col=q&127, c=q>>7;
            int j=c&(hs-1), g=c>>(stp-2);
            dif8(S,tw,(g*(hs<<3)+j)*SP+col,SP,j,hs,stp);
        }
        __syncthreads();
    }
    for(int q=tid;q<8192;q+=1024){
        int col=q&127, g=q>>7;
        int i0=(2*g)*SP+col, i1=i0+SP;
        float2 u=S[i0], v=S[i1];
        S[i0]=cadd(u,v); S[i1]=csub(u,v);
    }
    __syncthreads();
    const float* xp0=g_xt+(size_t)bc0*HWX;
    const float* xp1=xp0+HWX;
    float* yo0=g_yspec+(size_t)bc0*HWX;
    float* yo1=yo0+HWX;
    const float scale=1.0f/128.0f;
    for(int q=tid;q<4096;q+=1024){
        int h=q>>5, w0=(q&31)*4;
        int hb=brev7(h);
        float2 z0=S[hb*SP+w0],   z1=S[hb*SP+w0+1];
        float2 z2=S[hb*SP+w0+2], z3=S[hb*SP+w0+3];
        float a0=z0.x*scale, a1=z1.x*scale, a2=z2.x*scale, a3=z3.x*scale;
        float e0=z0.y*scale, e1=z1.y*scale, e2=z2.y*scale, e3=z3.y*scale;
#pragma unroll
        for(int dy=-1;dy<=1;++dy){
            int hh=h+dy;
            if((unsigned)hh<128u){
                const float* rp0=xp0+hh*128+w0;
                const float* rp1=xp1+hh*128+w0;
                float l0=(w0>0)?rp0[-1]:0.0f, r0=(w0<124)?rp0[4]:0.0f;
                float l1=(w0>0)?rp1[-1]:0.0f, r1=(w0<124)?rp1[4]:0.0f;
                float4 m0=*reinterpret_cast<const float4*>(rp0);
                float4 m1=*reinterpret_cast<const float4*>(rp1);
                float c00=cw0[(dy+1)*3+0], c01=cw0[(dy+1)*3+1], c02=cw0[(dy+1)*3+2];
                float c10=cw1[(dy+1)*3+0], c11=cw1[(dy+1)*3+1], c12=cw1[(dy+1)*3+2];
                a0=fmaf(c00,l0,  fmaf(c01,m0.x,fmaf(c02,m0.y,a0)));
                a1=fmaf(c00,m0.x,fmaf(c01,m0.y,fmaf(c02,m0.z,a1)));
                a2=fmaf(c00,m0.y,fmaf(c01,m0.z,fmaf(c02,m0.w,a2)));
                a3=fmaf(c00,m0.z,fmaf(c01,m0.w,fmaf(c02,r0,  a3)));
                e0=fmaf(c10,l1,  fmaf(c11,m1.x,fmaf(c12,m1.y,e0)));
                e1=fmaf(c10,m1.x,fmaf(c11,m1.y,fmaf(c12,m1.z,e1)));
                e2=fmaf(c10,m1.y,fmaf(c11,m1.z,fmaf(c12,m1.w,e2)));
                e3=fmaf(c10,m1.z,fmaf(c11,m1.w,fmaf(c12,r1,  e3)));
            }
        }
        *reinterpret_cast<float4*>(yo0+h*128+w0)=make_float4(a0,a1,a2,a3);
        *reinterpret_cast<float4*>(yo1+h*128+w0)=make_float4(e0,e1,e2,e3);
    }
}

/* ---------------- HMMA pointwise GEMM (cp.async) + in-kernel yspec transpose + LN ---------------- */
#define PB_AH 0
#define PB_AL 10240
#define PB_BH 20480
#define PB_BL 40960
#define PB_SZ 61440
#define FS_AUX 122880
#define FS_SUM (FS_AUX+0)
#define FS_SQ  (FS_AUX+2048)
#define FS_MR  (FS_AUX+4096)
#define FS_LB  (FS_AUX+5120)
#define FS_WGT (FS_AUX+6144)
#define FS_BSH (FS_AUX+7168)
#define FIN_SMEM (FS_AUX+8192)
#define ASTR 40
#define YSTR 132

__global__ void __launch_bounds__(512,1) k_final_hmma(
        const float* __restrict__ linb, const float* __restrict__ timev,
        const float* __restrict__ nww, const float* __restrict__ nwb,
        const float* __restrict__ nbw, const float* __restrict__ nbb,
        float* __restrict__ out){
    extern __shared__ __align__(16) char smem[];
    float* s_sum=(float*)(smem+FS_SUM);
    float* s_sq =(float*)(smem+FS_SQ);
    float* s_mr =(float*)(smem+FS_MR);
    float* s_lb =(float*)(smem+FS_LB);
    float* s_wgt=(float*)(smem+FS_WGT);
    float* s_bsh=(float*)(smem+FS_BSH);
    float* s_y  =(float*)smem;
    uint32_t uS=smem_u32(smem);

    int tid=threadIdx.x, lane=tid&31, wid=tid>>5;
    int warp_m=wid&3, warp_n=wid>>2;
    int b=blockIdx.y, p0=blockIdx.x*128;
    float tv=timev[b];
    for(int c=tid;c<CC;c+=512){
        s_lb[c]=linb[c];
        s_wgt[c]=tv*nww[c]+nwb[c];
        s_bsh[c]=tv*nbw[c]+nbb[c];
    }
    float acc[2][8][4];
#pragma unroll
    for(int i=0;i<2;++i)
#pragma unroll
        for(int j=0;j<8;++j)
#pragma unroll
            for(int k=0;k<4;++k) acc[i][j][k]=0.0f;

    const __nv_bfloat16* xh=g_xhi+((size_t)b*HWX+p0)*CC;
    const __nv_bfloat16* xl=g_xlo+((size_t)b*HWX+p0)*CC;
    int r=tid>>2, part=tid&3;
    uint32_t soff=(uint32_t)((r*ASTR+part*8)*2);
    size_t goffA=(size_t)r*CC+part*8;

    auto issue=[&](int kc){
        uint32_t base=(kc&1)*PB_SZ;
        CPA16(uS+base+PB_AH+soff, xh+goffA+kc*32);
        CPA16(uS+base+PB_AL+soff, xl+goffA+kc*32);
#pragma unroll
        for(int i=0;i<2;++i){
            int n=r+i*128;
            uint32_t so2=(uint32_t)((n*ASTR+part*8)*2);
            CPA16(uS+base+PB_BH+so2, g_whi+(size_t)n*CC+kc*32+part*8);
            CPA16(uS+base+PB_BL+so2, g_wlo+(size_t)n*CC+kc*32+part*8);
        }
        CPA_COMMIT();
    };
    issue(0);
    for(int kc=0;kc<8;++kc){
        if(kc<7){ issue(kc+1); CPA_WAIT(1); }
        else CPA_WAIT(0);
        __syncthreads();
        uint32_t base=(kc&1)*PB_SZ;
#pragma unroll
        for(int k16=0;k16<2;++k16){
            uint32_t ah[2][4], al[2][4];
#pragma unroll
            for(int mb=0;mb<2;++mb){
                uint32_t off=(uint32_t)(((warp_m*32+mb*16+(lane&15))*ASTR + (lane>>4)*8 + k16*16)*2);
                LDM4(ah[mb],uS+base+PB_AH+off);
                LDM4(al[mb],uS+base+PB_AL+off);
            }
#pragma unroll
            for(int nb=0;nb<4;++nb){
                uint32_t bh[4], bl[4];
                uint32_t off=(uint32_t)(((warp_n*64+nb*16+(lane&15))*ASTR + (lane>>4)*8 + k16*16)*2);
                LDM4(bh,uS+base+PB_BH+off);
                LDM4(bl,uS+base+PB_BL+off);
#pragma unroll
                for(int mb=0;mb<2;++mb){
#pragma unroll
                    for(int sub=0;sub<2;++sub){
                        float* d=acc[mb][nb*2+sub];
                        MMA16816(d,ah[mb],bh[sub],bh[sub+2]);
                        MMA16816(d,ah[mb],bl[sub],bl[sub+2]);
                        MMA16816(d,al[mb],bh[sub],bh[sub+2]);
                    }
                }
            }
        }
        __syncthreads();
    }
    /* in-kernel yspec transpose-add: two rounds of 128 channels from (B,C,HW) */
    for(int rr=0;rr<2;++rr){
        for(int j=0;j<8;++j){
            int q=tid+j*512;
            int c=q>>5, pw=(q&31)*4;
            float4 v=*reinterpret_cast<const float4*>(
                g_yspec+((size_t)b*CC+rr*128+c)*HWX+p0+pw);
            *reinterpret_cast<float4*>(s_y+(size_t)c*YSTR+pw)=v;
        }
        __syncthreads();
        if((warp_n>>1)==rr){
#pragma unroll
            for(int mb=0;mb<2;++mb){
#pragma unroll
                for(int half=0;half<2;++half){
                    int row=warp_m*32+mb*16+half*8+(lane>>2);
#pragma unroll
                    for(int nf=0;nf<8;++nf){
                        int cl=(warp_n&1)*64+nf*8+2*(lane&3);
                        acc[mb][nf][half*2+0]+=s_y[(size_t)cl*YSTR+row];
                        acc[mb][nf][half*2+1]+=s_y[(size_t)(cl+1)*YSTR+row];
                    }
                }
            }
        }
        __syncthreads();
    }
    /* bias add + row stats */
#pragma unroll
    for(int mb=0;mb<2;++mb){
#pragma unroll
        for(int half=0;half<2;++half){
            int row=warp_m*32+mb*16+half*8+(lane>>2);
            float rs=0.0f, rq=0.0f;
#pragma unroll
            for(int nf=0;nf<8;++nf){
                int c=warp_n*64+nf*8+2*(lane&3);
                float v0=acc[mb][nf][half*2+0]+s_lb[c];
                float v1=acc[mb][nf][half*2+1]+s_lb[c+1];
                acc[mb][nf][half*2+0]=v0;
                acc[mb][nf][half*2+1]=v1;
                rs+=v0+v1; rq+=v0*v0+v1*v1;
            }
            rs+=__shfl_xor_sync(0xffffffffu,rs,1);
            rs+=__shfl_xor_sync(0xffffffffu,rs,2);
            rq+=__shfl_xor_sync(0xffffffffu,rq,1);
            rq+=__shfl_xor_sync(0xffffffffu,rq,2);
            if((lane&3)==0){
                s_sum[warp_n*128+row]=rs;
                s_sq [warp_n*128+row]=rq;
            }
        }
    }
    __syncthreads();
    if(tid<128){
        float s=0.0f,q=0.0f;
#pragma unroll
        for(int w=0;w<4;++w){ s+=s_sum[w*128+tid]; q+=s_sq[w*128+tid]; }
        float mean=s*(1.0f/256.0f);
        float var=q*(1.0f/256.0f)-mean*mean;
        s_mr[tid]=mean;
        s_mr[128+tid]=rsqrtf(var+1e-5f);
    }
    __syncthreads();
#pragma unroll
    for(int mb=0;mb<2;++mb){
#pragma unroll
        for(int half=0;half<2;++half){
            int row=warp_m*32+mb*16+half*8+(lane>>2);
            float mn=s_mr[row], rst=s_mr[128+row];
            size_t base=((size_t)b*HWX+p0+row)*CC;
#pragma unroll
            for(int nf=0;nf<8;++nf){
                int c=warp_n*64+nf*8+2*(lane&3);
                float2 o;
                o.x=s_wgt[c]  *((acc[mb][nf][half*2+0]-mn)*rst)+s_bsh[c];
                o.y=s_wgt[c+1]*((acc[mb][nf][half*2+1]-mn)*rst)+s_bsh[c+1];
                *reinterpret_cast<float2*>(out+base+c)=o;
            }
        }
    }
}

extern "C" void kernel_launch(void* const* d_in, const int* in_sizes, int n_in,
                              void* d_out, int out_size){
    const float* x      =(const float*)d_in[0];
    const float* timev  =(const float*)d_in[1];
    const float* w_real =(const float*)d_in[2];
    const float* w_imag =(const float*)d_in[3];
    const float* conv_w =(const float*)d_in[4];
    const float* lin_w  =(const float*)d_in[5];
    const float* lin_b  =(const float*)d_in[6];
    const float* mlp_w1 =(const float*)d_in[7];
    const float* mlp_b1 =(const float*)d_in[8];
    const float* mlp_w2 =(const float*)d_in[9];
    const float* mlp_b2 =(const float*)d_in[10];
    const float* norm_ww=(const float*)d_in[11];
    const float* norm_wb=(const float*)d_in[12];
    const float* norm_bw=(const float*)d_in[13];
    const float* norm_bb=(const float*)d_in[14];
    const float* kx     =(const float*)d_in[15];
    const float* ky     =(const float*)d_in[16];
    float* out=(float*)d_out;

    const int FFT_SMEM=(128*SP+64)*sizeof(float2);
    cudaFuncSetAttribute(k_fft_fwd,cudaFuncAttributeMaxDynamicSharedMemorySize,FFT_SMEM);
    cudaFuncSetAttribute(k_fft_inv,cudaFuncAttributeMaxDynamicSharedMemorySize,FFT_SMEM);
    cudaFuncSetAttribute(k_final_hmma,cudaFuncAttributeMaxDynamicSharedMemorySize,FIN_SMEM);
    cudaFuncSetAttribute(k_cgemm_hmma,cudaFuncAttributeMaxDynamicSharedMemorySize,CG_SMEM);

    k_init<<<1,1024>>>();
    {
        dim3 g(HWX/32,CC/32,BB), blk(32,8);
        k_transpose<<<g,blk>>>(x);
    }
    k_split3<<<(3*CC*CC+255)/256,256>>>(lin_w,w_real,w_imag);
    k_fft_fwd<<<BB*CC/2,512,FFT_SMEM>>>(mlp_w1,mlp_b1,mlp_w2,mlp_b2);
    {
        dim3 g((FF+63)/64,CC/128,BB);
        k_cgemm_hmma<<<g,256,CG_SMEM>>>(kx,ky);
    }
    k_fft_inv<<<BB*CC/2,1024,FFT_SMEM>>>(conv_w,kx,ky);
    {
        dim3 g(HWX/128,BB);
        k_final_hmma<<<g,512,FIN_SMEM>>>(lin_b,timev,norm_ww,norm_wb,norm_bw,norm_bb,out);
    }
}

// round 16
// speedup vs baseline: 1.2256x; 1.0588x over previous
#include <cuda_runtime.h>
#include <cuda_bf16.h>
#include <math.h>
#include <stdint.h>

#define BB 4
#define CC 256
#define HWX 16384
#define HF 128
#define WF 65
#define FF (HF*WF)
#define NB 6
#define GH 128
#define SP 129

typedef unsigned long long ull;

__device__ float  g_xt[(size_t)BB*CC*HWX];
__device__ float2 g_Xf[(size_t)BB*CC*FF];
__device__ float2 g_Xmap[(size_t)BB*CC*FF];
__device__ float  g_yspec[(size_t)BB*CC*HWX];
__device__ __nv_bfloat16 g_xhi[(size_t)BB*CC*HWX];
__device__ __nv_bfloat16 g_xlo[(size_t)BB*CC*HWX];
__device__ __nv_bfloat16 g_whi[CC*CC];
__device__ __nv_bfloat16 g_wlo[CC*CC];
__device__ __nv_bfloat16 g_wrh[CC*CC];
__device__ __nv_bfloat16 g_wrl[CC*CC];
__device__ __nv_bfloat16 g_wih[CC*CC];
__device__ __nv_bfloat16 g_wil[CC*CC];
__device__ float  g_alpha[BB*CC*NB];
__device__ int    g_bid[FF];
__device__ float  g_cnt[NB];

__device__ __forceinline__ float2 cmul(float2 a, float2 b){return make_float2(a.x*b.x-a.y*b.y,a.x*b.y+a.y*b.x);}
__device__ __forceinline__ float2 cadd(float2 a, float2 b){return make_float2(a.x+b.x,a.y+b.y);}
__device__ __forceinline__ float2 csub(float2 a, float2 b){return make_float2(a.x-b.x,a.y-b.y);}
__device__ __forceinline__ int brev7(int x){return (int)(__brev((unsigned)x)>>25);}
__device__ __forceinline__ float sigm(float x){return 1.0f/(1.0f+expf(-x));}

__device__ __forceinline__ uint32_t smem_u32(const void* p){
    uint32_t a;asm("{ .reg .u64 t; cvta.to.shared.u64 t, %1; cvt.u32.u64 %0, t; }":"=r"(a):"l"(p));return a;
}
#define LDM4(d,adr) asm volatile("ldmatrix.sync.aligned.m8n8.x4.shared.b16 {%0,%1,%2,%3},[%4];" \
    :"=r"((d)[0]),"=r"((d)[1]),"=r"((d)[2]),"=r"((d)[3]):"r"(adr))
#define MMA16816(d,a,b0,b1) asm volatile( \
    "mma.sync.aligned.m16n8k16.row.col.f32.bf16.bf16.f32 {%0,%1,%2,%3},{%4,%5,%6,%7},{%8,%9},{%0,%1,%2,%3};" \
    : "+f"((d)[0]),"+f"((d)[1]),"+f"((d)[2]),"+f"((d)[3]) \
    : "r"((a)[0]),"r"((a)[1]),"r"((a)[2]),"r"((a)[3]),"r"(b0),"r"(b1))
#define CPA16(dst,src) asm volatile("cp.async.cg.shared.global [%0],[%1],16;"::"r"(dst),"l"(src))
#define CPA_COMMIT()   asm volatile("cp.async.commit_group;":::"memory")
#define CPA_WAIT(n)    asm volatile("cp.async.wait_group %0;"::"n"(n):"memory")

/* band table: bit-exact float32 replica of the numpy band partition */
__global__ void k_init(){
    __shared__ int cnt[NB];
    int tid=threadIdx.x;
    if(tid<NB) cnt[tid]=0;
    __syncthreads();
    const float rmax=__fsqrt_rn(2.0f);
    for(int f=tid;f<FF;f+=blockDim.x){
        int h=f/WF, w=f-(f/WF)*WF;
        float a=__fdiv_rn((float)h,127.0f);
        float b=__fdiv_rn((float)w,64.0f);
        float s=__fadd_rn(__fmul_rn(a,a),__fmul_rn(b,b));
        float r=__fsqrt_rn(s);
        float rn=__fdiv_rn(r,rmax);
        int bd=(int)floorf(__fmul_rn(rn,6.0f));
        if(bd>NB-1) bd=NB-1;
        g_bid[f]=bd;
        atomicAdd(&cnt[bd],1);
    }
    __syncthreads();
    if(tid<NB) g_cnt[tid]=(float)max(cnt[tid],1);
}

/* (B,HW,C) -> (B,C,HW), fused bf16 hi/lo split kept in (B,HW,C) */
__global__ void k_transpose(const float* __restrict__ x){
    __shared__ float t[32][33];
    int b=blockIdx.z, p0=blockIdx.x*32, c0=blockIdx.y*32;
    int tx=threadIdx.x, ty=threadIdx.y;
#pragma unroll
    for(int i=0;i<32;i+=8){
        size_t idx=((size_t)b*HWX+(p0+ty+i))*CC+c0+tx;
        float v=x[idx];
        t[ty+i][tx]=v;
        __nv_bfloat16 h=__float2bfloat16(v);
        g_xhi[idx]=h;
        g_xlo[idx]=__float2bfloat16(v-__bfloat162float(h));
    }
    __syncthreads();
#pragma unroll
    for(int i=0;i<32;i+=8) g_xt[((size_t)b*CC+(c0+ty+i))*HWX+p0+tx]=t[tx][ty+i];
}

/* split all three weight matrices in one launch */
__global__ void k_split3(const float* __restrict__ w0,const float* __restrict__ w1,const float* __restrict__ w2){
    int i=blockIdx.x*blockDim.x+threadIdx.x;
    int m=i>>16, r=i&65535;
    if(m>2) return;
    const float* src=(m==0)?w0:(m==1)?w1:w2;
    __nv_bfloat16* hi=(m==0)?g_whi:(m==1)?g_wrh:g_wih;
    __nv_bfloat16* lo=(m==0)?g_wlo:(m==1)?g_wrl:g_wil;
    float v=src[r];
    __nv_bfloat16 h=__float2bfloat16(v);
    hi[r]=h;
    lo[r]=__float2bfloat16(v-__bfloat162float(h));
}

/* ---- radix-8 triple-stage butterflies (DIT rows / DIF cols) ---- */
__device__ __forceinline__ void dit8(float2* S,const float2* tw,int base,int half,int j,int s){
    float2 x0=S[base],x1=S[base+half],x2=S[base+2*half],x3=S[base+3*half];
    float2 x4=S[base+4*half],x5=S[base+5*half],x6=S[base+6*half],x7=S[base+7*half];
    float2 w1=tw[j<<(6-s)];
    float2 t1=cmul(w1,x1),t3=cmul(w1,x3),t5=cmul(w1,x5),t7=cmul(w1,x7);
    float2 a0=cadd(x0,t1),a1=csub(x0,t1),a2=cadd(x2,t3),a3=csub(x2,t3);
    float2 a4=cadd(x4,t5),a5=csub(x4,t5),a6=cadd(x6,t7),a7=csub(x6,t7);
    float2 w2a=tw[j<<(5-s)],w2b=tw[(j+half)<<(5-s)];
    float2 u2=cmul(w2a,a2),u3=cmul(w2b,a3),u6=cmul(w2a,a6),u7=cmul(w2b,a7);
    float2 b0=cadd(a0,u2),b2=csub(a0,u2),b1=cadd(a1,u3),b3=csub(a1,u3);
    float2 b4=cadd(a4,u6),b6=csub(a4,u6),b5=cadd(a5,u7),b7=csub(a5,u7);
    float2 w30=tw[j<<(4-s)],w31=tw[(j+half)<<(4-s)],w32=tw[(j+2*half)<<(4-s)],w33=tw[(j+3*half)<<(4-s)];
    float2 v4=cmul(w30,b4),v5=cmul(w31,b5),v6=cmul(w32,b6),v7=cmul(w33,b7);
    S[base]=cadd(b0,v4);        S[base+4*half]=csub(b0,v4);
    S[base+half]=cadd(b1,v5);   S[base+5*half]=csub(b1,v5);
    S[base+2*half]=cadd(b2,v6); S[base+6*half]=csub(b2,v6);
    S[base+3*half]=cadd(b3,v7); S[base+7*half]=csub(b3,v7);
}
__device__ __forceinline__ void dif8(float2* S,const float2* tw,int i0,int strd,int j,int hs,int stp){
    float2 x0=S[i0],x1=S[i0+hs*strd],x2=S[i0+2*hs*strd],x3=S[i0+3*hs*strd];
    float2 x4=S[i0+4*hs*strd],x5=S[i0+5*hs*strd],x6=S[i0+6*hs*strd],x7=S[i0+7*hs*strd];
    float2 a0=cadd(x0,x4), a4=cmul(tw[(j     )<<(6-stp)],csub(x0,x4));
    float2 a1=cadd(x1,x5), a5=cmul(tw[(j+hs  )<<(6-stp)],csub(x1,x5));
    float2 a2=cadd(x2,x6), a6=cmul(tw[(j+2*hs)<<(6-stp)],csub(x2,x6));
    float2 a3=cadd(x3,x7), a7=cmul(tw[(j+3*hs)<<(6-stp)],csub(x3,x7));
    float2 wb0=tw[j<<(7-stp)], wb1=tw[(j+hs)<<(7-stp)];
    float2 b0=cadd(a0,a2), b2=cmul(wb0,csub(a0,a2));
    float2 b1=cadd(a1,a3), b3=cmul(wb1,csub(a1,a3));
    float2 b4=cadd(a4,a6), b6=cmul(wb0,csub(a4,a6));
    float2 b5=cadd(a5,a7), b7=cmul(wb1,csub(a5,a7));
    float2 wc=tw[j<<(8-stp)];
    S[i0]=cadd(b0,b1);           S[i0+hs*strd]=cmul(wc,csub(b0,b1));
    S[i0+2*hs*strd]=cadd(b2,b3); S[i0+3*hs*strd]=cmul(wc,csub(b2,b3));
    S[i0+4*hs*strd]=cadd(b4,b5); S[i0+5*hs*strd]=cmul(wc,csub(b4,b5));
    S[i0+6*hs*strd]=cadd(b6,b7); S[i0+7*hs*strd]=cmul(wc,csub(b6,b7));
}

/* -------- forward (512 thr): packed complex FFT2 + band sums + fused gate MLP -------- */
__global__ void __launch_bounds__(512) k_fft_fwd(const float* __restrict__ mw1,const float* __restrict__ mb1,
                                                  const float* __restrict__ mw2,const float* __restrict__ mb2){
    extern __shared__ __align__(16) float2 sm[];
    float2* S=sm; float2* tw=sm+128*SP;
    __shared__ float wsum[16][2*NB];
    __shared__ float means[2*NB], hb[2*GH];
    int tid=threadIdx.x;
    int lane=tid&31, wid=tid>>5;
    int bc0=blockIdx.x*2;
    const float* x0=g_xt+(size_t)bc0*HWX;
    const float* x1=x0+HWX;
    if(tid<64){float s,c;sincospif(-(float)tid/64.0f,&s,&c);tw[tid]=make_float2(c,s);}
    for(int idx=tid;idx<HWX;idx+=512){
        int h=idx>>7, w=idx&127;
        S[h*SP+brev7(w)]=make_float2(x0[idx],x1[idx]);
    }
    __syncthreads();
    for(int s=0;s<6;s+=3){
        int half=1<<s;
        for(int q=tid;q<2048;q+=512){
            int row=q&127, c=q>>7;
            int j=c&(half-1), g=c>>s;
            dit8(S,tw,row*SP+g*(half<<3)+j,half,j,s);
        }
        __syncthreads();
    }
    for(int q=tid;q<8192;q+=512){
        int row=q&127, j=q>>7;
        int i0=row*SP+j, i1=i0+64;
        float2 wv=tw[j];
        float2 u=S[i0], v=cmul(wv,S[i1]);
        S[i0]=cadd(u,v); S[i1]=csub(u,v);
    }
    __syncthreads();
    for(int stp=6;stp>=3;stp-=3){
        int hs=1<<(stp-2);
        for(int q=tid;q<2048;q+=512){
            int col=q&127, c=q>>7;
            int j=c&(hs-1), g=c>>(stp-2);
            dif8(S,tw,(g*(hs<<3)+j)*SP+col,SP,j,hs,stp);
        }
        __syncthreads();
    }
    for(int q=tid;q<8192;q+=512){
        int col=q&127, g=q>>7;
        int i0=(2*g)*SP+col, i1=i0+SP;
        float2 u=S[i0], v=S[i1];
        S[i0]=cadd(u,v); S[i1]=csub(u,v);
    }
    __syncthreads();
    float acc[2*NB];
#pragma unroll
    for(int k=0;k<2*NB;++k) acc[k]=0.0f;
    const float hs2=0.5f/128.0f;
    float2* Xo0=g_Xf+(size_t)bc0*FF;
    float2* Xo1=Xo0+FF;
    for(int idx=tid;idx<FF;idx+=512){
        int hf=idx/WF, w=idx-hf*WF;
        float2 Z1=S[brev7(hf)*SP+w];
        int h2=(128-hf)&127, w2=(128-w)&127;
        float2 Z2=S[brev7(h2)*SP+w2];
        float2 v0=make_float2((Z1.x+Z2.x)*hs2,(Z1.y-Z2.y)*hs2);
        float2 v1=make_float2((Z1.y+Z2.y)*hs2,(Z2.x-Z1.x)*hs2);
        Xo0[idx]=v0; Xo1[idx]=v1;
        float m0=sqrtf(v0.x*v0.x+v0.y*v0.y);
        float m1=sqrtf(v1.x*v1.x+v1.y*v1.y);
        int bd=g_bid[idx];
#pragma unroll
        for(int k=0;k<NB;++k){
            acc[k]   +=(bd==k)?m0:0.0f;
            acc[NB+k]+=(bd==k)?m1:0.0f;
        }
    }
#pragma unroll
    for(int k=0;k<2*NB;++k){
        float v=acc[k];
#pragma unroll
        for(int o=16;o;o>>=1) v+=__shfl_xor_sync(0xffffffffu,v,o);
        if(lane==0) wsum[wid][k]=v;
    }
    __syncthreads();
    if(tid<2*NB){
        float s=0.0f;
#pragma unroll
        for(int w=0;w<16;++w) s+=wsum[w][tid];
        int k=tid%NB;
        means[tid]=s/(g_cnt[k]+1e-6f);
    }
    __syncthreads();
    if(tid<2*GH){
        int ch=tid>>7, hh=tid&127;
        float hv=mb1[hh];
#pragma unroll
        for(int n=0;n<NB;++n) hv+=mw1[hh*NB+n]*means[ch*NB+n];
        hb[tid]=fmaxf(hv,0.0f);
    }
    __syncthreads();
    if(wid<2*NB){
        int ch=wid/NB, n=wid-ch*NB;
        float v=0.0f;
#pragma unroll
        for(int i=0;i<4;++i){int hh=lane+32*i; v+=mw2[n*GH+hh]*hb[ch*GH+hh];}
#pragma unroll
        for(int o=16;o;o>>=1) v+=__shfl_xor_sync(0xffffffffu,v,o);
        if(lane==0) g_alpha[(bc0+ch)*NB+n]=1.0f/(1.0f+expf(-(v+mb2[n])));
    }
}

/* ---------------- HMMA complex GEMM on masked freqs ---------------- */
#define CG_XRH 0
#define CG_XRL 5120
#define CG_XIH 10240
#define CG_XIL 15360
#define CG_W   20480
#define CG_SMEM 81920

__global__ void __launch_bounds__(256) k_cgemm_hmma(const float* __restrict__ kxp,const float* __restrict__ kyp){
    extern __shared__ __align__(16) char smc[];
    int kxi=(int)floorf(sigm(kxp[0])*128.0f);
    int kyi=(int)floorf(sigm(kyp[0])*65.0f);
    int NC=kxi*kyi;
    int f0=blockIdx.x*64;
    if(f0>=NC) return;
    int c0=blockIdx.y*128, b=blockIdx.z;
    __shared__ int fmap[64];
    int tid=threadIdx.x, lane=tid&31, wid=tid>>5;
    int warp_m=wid&1, warp_n=wid>>1;
    if(tid<64){
        int f=f0+tid;
        fmap[tid]=(f<NC)?((f/kyi)*WF+(f-(f/kyi)*kyi)):-1;
    }
    __nv_bfloat16* sX=(__nv_bfloat16*)smc;
    uint32_t uX=smem_u32(smc);
    float accR[2][4][4], accI[2][4][4];
#pragma unroll
    for(int i=0;i<2;++i)
#pragma unroll
        for(int j=0;j<4;++j)
#pragma unroll
            for(int k=0;k<4;++k){accR[i][j][k]=0.0f;accI[i][j][k]=0.0f;}
    __syncthreads();

    const __nv_bfloat16* gW[4]={g_wrh,g_wrl,g_wih,g_wil};
    for(int kc=0;kc<8;++kc){
        int k0=kc*32;
        {
            int fi=tid&63, ds=tid>>6;
            int mp=fmap[fi];
#pragma unroll
            for(int i=0;i<8;++i){
                int d=ds*8+i;
                float2 v=make_float2(0.0f,0.0f);
                if(mp>=0) v=g_Xf[((size_t)(b*CC+k0+d))*FF+mp];
                __nv_bfloat16 hr=__float2bfloat16(v.x);
                __nv_bfloat16 hi=__float2bfloat16(v.y);
                sX[CG_XRH/2+fi*40+d]=hr;
                sX[CG_XRL/2+fi*40+d]=__float2bfloat16(v.x-__bfloat162float(hr));
                sX[CG_XIH/2+fi*40+d]=hi;
                sX[CG_XIL/2+fi*40+d]=__float2bfloat16(v.y-__bfloat162float(hi));
            }
        }
#pragma unroll
        for(int m=0;m<4;++m){
#pragma unroll
            for(int j=0;j<2;++j){
                int idx=tid+j*256;
                int row=idx>>2, part=idx&3;
                uint4 val=*reinterpret_cast<const uint4*>(gW[m]+(size_t)(c0+row)*CC+k0+part*8);
                *reinterpret_cast<uint4*>(smc+CG_W+m*10240+(row*40+part*8)*2)=val;
                if(m>=2){
                    uint4 nv=val;
                    nv.x^=0x80008000u; nv.y^=0x80008000u; nv.z^=0x80008000u; nv.w^=0x80008000u;
                    *reinterpret_cast<uint4*>(smc+CG_W+(m+2)*10240+(row*40+part*8)*2)=nv;
                }
            }
        }
        __syncthreads();
#pragma unroll
        for(int k16=0;k16<2;++k16){
            uint32_t xrh[2][4],xrl[2][4],xih[2][4],xil[2][4];
#pragma unroll
            for(int mb=0;mb<2;++mb){
                uint32_t off=(uint32_t)(((warp_m*32+mb*16+(lane&15))*40+(lane>>4)*8+k16*16)*2);
                LDM4(xrh[mb],uX+CG_XRH+off);
                LDM4(xrl[mb],uX+CG_XRL+off);
                LDM4(xih[mb],uX+CG_XIH+off);
                LDM4(xil[mb],uX+CG_XIL+off);
            }
#pragma unroll
            for(int ng=0;ng<2;++ng){
                uint32_t wrh[4],wrl[4],wih[4],wil[4],wnh[4],wnl[4];
                uint32_t off=(uint32_t)(((warp_n*32+ng*16+(lane&15))*40+(lane>>4)*8+k16*16)*2);
                LDM4(wrh,uX+CG_W+0*10240+off);
                LDM4(wrl,uX+CG_W+1*10240+off);
                LDM4(wih,uX+CG_W+2*10240+off);
                LDM4(wil,uX+CG_W+3*10240+off);
                LDM4(wnh,uX+CG_W+4*10240+off);
                LDM4(wnl,uX+CG_W+5*10240+off);
#pragma unroll
                for(int mb=0;mb<2;++mb){
#pragma unroll
                    for(int sub=0;sub<2;++sub){
                        float* dR=accR[mb][ng*2+sub];
                        float* dI=accI[mb][ng*2+sub];
                        MMA16816(dR,xrh[mb],wrh[sub],wrh[sub+2]);
                        MMA16816(dR,xrh[mb],wrl[sub],wrl[sub+2]);
                        MMA16816(dR,xrl[mb],wrh[sub],wrh[sub+2]);
                        MMA16816(dR,xih[mb],wnh[sub],wnh[sub+2]);
                        MMA16816(dR,xih[mb],wnl[sub],wnl[sub+2]);
                        MMA16816(dR,xil[mb],wnh[sub],wnh[sub+2]);
                        MMA16816(dI,xih[mb],wrh[sub],wrh[sub+2]);
                        MMA16816(dI,xih[mb],wrl[sub],wrl[sub+2]);
                        MMA16816(dI,xil[mb],wrh[sub],wrh[sub+2]);
                        MMA16816(dI,xrh[mb],wih[sub],wih[sub+2]);
                        MMA16816(dI,xrh[mb],wil[sub],wil[sub+2]);
                        MMA16816(dI,xrl[mb],wih[sub],wih[sub+2]);
                    }
                }
            }
        }
        __syncthreads();
    }
    float2* sO=(float2*)smc;
#pragma unroll
    for(int mb=0;mb<2;++mb){
#pragma unroll
        for(int half=0;half<2;++half){
            int f=warp_m*32+mb*16+half*8+(lane>>2);
#pragma unroll
            for(int nf=0;nf<4;++nf){
                int c=warp_n*32+nf*8+2*(lane&3);
                sO[(size_t)c*66+f]    =make_float2(accR[mb][nf][half*2+0],accI[mb][nf][half*2+0]);
                sO[(size_t)(c+1)*66+f]=make_float2(accR[mb][nf][half*2+1],accI[mb][nf][half*2+1]);
            }
        }
    }
    __syncthreads();
    for(int it=0;it<32;++it){
        int idx=tid+it*256;
        int c=idx>>6, f=idx&63;
        if(f0+f<NC)
            g_Xmap[((size_t)(b*CC+c0+c))*FF+f0+f]=sO[(size_t)c*66+f];
    }
}

/* fused-spectrum value at (hf,wf) for the channel pair */
__device__ __forceinline__ void fuse_pair(int hf,int wf,int kxi,int kyi,
        const float2* __restrict__ Xf0,const float2* __restrict__ Xf1,
        const float2* __restrict__ Xm0,const float2* __restrict__ Xm1,
        const float* al0,const float* al1,float2&v0,float2&v1){
    int fidx=hf*WF+wf;
    int bd=g_bid[fidx];
    if(hf<kxi && wf<kyi){
        int ci=hf*kyi+wf;
        float a0=al0[bd], a1=al1[bd];
        float2 m0=Xm0[ci], m1=Xm1[ci];
        v0=make_float2(a0*m0.x,a0*m0.y);
        v1=make_float2(a1*m1.x,a1*m1.y);
    } else {
        float b0=1.0f-al0[bd], b1=1.0f-al1[bd];
        float2 q0=Xf0[fidx], q1=Xf1[fidx];
        v0=make_float2(b0*q0.x,b0*q0.y);
        v1=make_float2(b1*q1.x,b1*q1.y);
    }
}

/* -------- inverse (1024 thr): single-read dual-write fuse + complex IFFT2 + conv -------- */
__global__ void __launch_bounds__(1024) k_fft_inv(const float* __restrict__ convw,
                                                 const float* __restrict__ kxp,const float* __restrict__ kyp){
    extern __shared__ __align__(16) float2 sm[];
    float2* S=sm; float2* tw=sm+128*SP;
    __shared__ float al0[NB], al1[NB], cw0[9], cw1[9];
    int tid=threadIdx.x;
    int bc0=blockIdx.x*2;
    int c0=bc0&(CC-1);
    if(tid<64){float s,cc;sincospif((float)tid/64.0f,&s,&cc);tw[tid]=make_float2(cc,s);}
    if(tid<NB)  al0[tid]=g_alpha[bc0*NB+tid];
    if(tid>=32&&tid<32+NB) al1[tid-32]=g_alpha[(bc0+1)*NB+(tid-32)];
    if(tid>=64&&tid<73)  cw0[tid-64]=convw[c0*9+(tid-64)];
    if(tid>=96&&tid<105) cw1[tid-96]=convw[(c0+1)*9+(tid-96)];
    int kxi=(int)floorf(sigm(kxp[0])*128.0f);
    int kyi=(int)floorf(sigm(kyp[0])*65.0f);
    __syncthreads();
    const float2* Xf0=g_Xf+(size_t)bc0*FF;   const float2* Xf1=Xf0+FF;
    const float2* Xm0=g_Xmap+(size_t)bc0*FF; const float2* Xm1=Xm0+FF;
    /* fuse each interior freq once; write primary + Hermitian mirror */
    for(int idx=tid;idx<FF;idx+=1024){
        int hf=idx/WF, wf=idx-hf*WF;
        if(wf==0||wf==64) continue;
        float2 v0,v1;
        fuse_pair(hf,wf,kxi,kyi,Xf0,Xf1,Xm0,Xm1,al0,al1,v0,v1);
        S[hf*SP+brev7(wf)]=make_float2(v0.x-v1.y, v0.y+v1.x);
        int h2=(128-hf)&127;
        S[h2*SP+brev7(128-wf)]=make_float2(v0.x+v1.y, v1.x-v0.y);
    }
    /* w in {0,64}: Hermitian projection along h; write pair */
    for(int t=tid;t<130;t+=1024){
        int w=(t<65)?0:64, hf=(t<65)?t:(t-65);
        float2 v0,v1,u0,u1;
        fuse_pair(hf,w,kxi,kyi,Xf0,Xf1,Xm0,Xm1,al0,al1,v0,v1);
        fuse_pair((128-hf)&127,w,kxi,kyi,Xf0,Xf1,Xm0,Xm1,al0,al1,u0,u1);
        float2 p0=make_float2((v0.x+u0.x)*0.5f,(v0.y-u0.y)*0.5f);
        float2 p1=make_float2((v1.x+u1.x)*0.5f,(v1.y-u1.y)*0.5f);
        int wb=brev7(w);
        S[hf*SP+wb]=make_float2(p0.x-p1.y, p0.y+p1.x);
        if(hf!=0&&hf!=64)
            S[(128-hf)*SP+wb]=make_float2(p0.x+p1.y, p1.x-p0.y);
    }
    __syncthreads();
    for(int s=0;s<6;s+=3){
        int half=1<<s;
        for(int q=tid;q<2048;q+=1024){
            int row=q&127, c=q>>7;
            int j=c&(half-1), g=c>>s;
            dit8(S,tw,row*SP+g*(half<<3)+j,half,j,s);
        }
        __syncthreads();
    }
    for(int q=tid;q<8192;q+=1024){
        int row=q&127, j=q>>7;
        int i0=row*SP+j, i1=i0+64;
        float2 wv=tw[j];
        float2 u=S[i0], v=cmul(wv,S[i1]);
        S[i0]=cadd(u,v); S[i1]=csub(u,v);
    }
    __syncthreads();
    for(int stp=6;stp>=3;stp-=3){
        int hs=1<<(stp-2);
        for(int q=tid;q<2048;q+=1024){
            int col=q&127, c=q>>7;
            int j=c&(hs-1), g=c>>(stp-2);
            dif8(S,tw,(g*(hs<<3)+j)*SP+col,SP,j,hs,stp);
        }
        __syncthreads();
    }
    for(int q=tid;q<8192;q+=1024){
        int col=q&127, g=q>>7;
        int i0=(2*g)*SP+col, i1=i0+SP;
        float2 u=S[i0], v=S[i1];
        S[i0]=cadd(u,v); S[i1]=csub(u,v);
    }
    __syncthreads();
    const float* xp0=g_xt+(size_t)bc0*HWX;
    const float* xp1=xp0+HWX;
    float* yo0=g_yspec+(size_t)bc0*HWX;
    float* yo1=yo0+HWX;
    const float scale=1.0f/128.0f;
    for(int q=tid;q<4096;q+=1024){
        int h=q>>5, w0=(q&31)*4;
        int hb=brev7(h);
        float2 z0=S[hb*SP+w0],   z1=S[hb*SP+w0+1];
        float2 z2=S[hb*SP+w0+2], z3=S[hb*SP+w0+3];
        float a0=z0.x*scale, a1=z1.x*scale, a2=z2.x*scale, a3=z3.x*scale;
        float e0=z0.y*scale, e1=z1.y*scale, e2=z2.y*scale, e3=z3.y*scale;
#pragma unroll
        for(int dy=-1;dy<=1;++dy){
            int hh=h+dy;
            if((unsigned)hh<128u){
                const float* rp0=xp0+hh*128+w0;
                const float* rp1=xp1+hh*128+w0;
                float l0=(w0>0)?rp0[-1]:0.0f, r0=(w0<124)?rp0[4]:0.0f;
                float l1=(w0>0)?rp1[-1]:0.0f, r1=(w0<124)?rp1[4]:0.0f;
                float4 m0=*reinterpret_cast<const float4*>(rp0);
                float4 m1=*reinterpret_cast<const float4*>(rp1);
                float c00=cw0[(dy+1)*3+0], c01=cw0[(dy+1)*3+1], c02=cw0[(dy+1)*3+2];
                float c10=cw1[(dy+1)*3+0], c11=cw1[(dy+1)*3+1], c12=cw1[(dy+1)*3+2];
                a0=fmaf(c00,l0,  fmaf(c01,m0.x,fmaf(c02,m0.y,a0)));
                a1=fmaf(c00,m0.x,fmaf(c01,m0.y,fmaf(c02,m0.z,a1)));
                a2=fmaf(c00,m0.y,fmaf(c01,m0.z,fmaf(c02,m0.w,a2)));
                a3=fmaf(c00,m0.z,fmaf(c01,m0.w,fmaf(c02,r0,  a3)));
                e0=fmaf(c10,l1,  fmaf(c11,m1.x,fmaf(c12,m1.y,e0)));
                e1=fmaf(c10,m1.x,fmaf(c11,m1.y,fmaf(c12,m1.z,e1)));
                e2=fmaf(c10,m1.y,fmaf(c11,m1.z,fmaf(c12,m1.w,e2)));
                e3=fmaf(c10,m1.z,fmaf(c11,m1.w,fmaf(c12,r1,  e3)));
            }
        }
        *reinterpret_cast<float4*>(yo0+h*128+w0)=make_float4(a0,a1,a2,a3);
        *reinterpret_cast<float4*>(yo1+h*128+w0)=make_float4(e0,e1,e2,e3);
    }
}

/* ---------------- HMMA pointwise GEMM (cp.async) + in-kernel yspec transpose + LN ---------------- */
#define PB_AH 0
#define PB_AL 10240
#define PB_BH 20480
#define PB_BL 40960
#define PB_SZ 61440
#define FS_AUX 122880
#define FS_SUM (FS_AUX+0)
#define FS_SQ  (FS_AUX+2048)
#define FS_MR  (FS_AUX+4096)
#define FS_LB  (FS_AUX+5120)
#define FS_WGT (FS_AUX+6144)
#define FS_BSH (FS_AUX+7168)
#define FIN_SMEM (FS_AUX+8192)
#define ASTR 40
#define YSTR 132

__global__ void __launch_bounds__(512,1) k_final_hmma(
        const float* __restrict__ linb, const float* __restrict__ timev,
        const float* __restrict__ nww, const float* __restrict__ nwb,
        const float* __restrict__ nbw, const float* __restrict__ nbb,
        float* __restrict__ out){
    extern __shared__ __align__(16) char smem[];
    float* s_sum=(float*)(smem+FS_SUM);
    float* s_sq =(float*)(smem+FS_SQ);
    float* s_mr =(float*)(smem+FS_MR);
    float* s_lb =(float*)(smem+FS_LB);
    float* s_wgt=(float*)(smem+FS_WGT);
    float* s_bsh=(float*)(smem+FS_BSH);
    float* s_y  =(float*)smem;
    uint32_t uS=smem_u32(smem);

    int tid=threadIdx.x, lane=tid&31, wid=tid>>5;
    int warp_m=wid&3, warp_n=wid>>2;
    int b=blockIdx.y, p0=blockIdx.x*128;
    float tv=timev[b];
    for(int c=tid;c<CC;c+=512){
        s_lb[c]=linb[c];
        s_wgt[c]=tv*nww[c]+nwb[c];
        s_bsh[c]=tv*nbw[c]+nbb[c];
    }
    float acc[2][8][4];
#pragma unroll
    for(int i=0;i<2;++i)
#pragma unroll
        for(int j=0;j<8;++j)
#pragma unroll
            for(int k=0;k<4;++k) acc[i][j][k]=0.0f;

    const __nv_bfloat16* xh=g_xhi+((size_t)b*HWX+p0)*CC;
    const __nv_bfloat16* xl=g_xlo+((size_t)b*HWX+p0)*CC;
    int r=tid>>2, part=tid&3;
    uint32_t soff=(uint32_t)((r*ASTR+part*8)*2);
    size_t goffA=(size_t)r*CC+part*8;

    auto issue=[&](int kc){
        uint32_t base=(kc&1)*PB_SZ;
        CPA16(uS+base+PB_AH+soff, xh+goffA+kc*32);
        CPA16(uS+base+PB_AL+soff, xl+goffA+kc*32);
#pragma unroll
        for(int i=0;i<2;++i){
            int n=r+i*128;
            uint32_t so2=(uint32_t)((n*ASTR+part*8)*2);
            CPA16(uS+base+PB_BH+so2, g_whi+(size_t)n*CC+kc*32+part*8);
            CPA16(uS+base+PB_BL+so2, g_wlo+(size_t)n*CC+kc*32+part*8);
        }
        CPA_COMMIT();
    };
    issue(0);
    for(int kc=0;kc<8;++kc){
        if(kc<7){ issue(kc+1); CPA_WAIT(1); }
        else CPA_WAIT(0);
        __syncthreads();
        uint32_t base=(kc&1)*PB_SZ;
#pragma unroll
        for(int k16=0;k16<2;++k16){
            uint32_t ah[2][4], al[2][4];
#pragma unroll
            for(int mb=0;mb<2;++mb){
                uint32_t off=(uint32_t)(((warp_m*32+mb*16+(lane&15))*ASTR + (lane>>4)*8 + k16*16)*2);
                LDM4(ah[mb],uS+base+PB_AH+off);
                LDM4(al[mb],uS+base+PB_AL+off);
            }
#pragma unroll
            for(int nb=0;nb<4;++nb){
                uint32_t bh[4], bl[4];
                uint32_t off=(uint32_t)(((warp_n*64+nb*16+(lane&15))*ASTR + (lane>>4)*8 + k16*16)*2);
                LDM4(bh,uS+base+PB_BH+off);
                LDM4(bl,uS+base+PB_BL+off);
#pragma unroll
                for(int mb=0;mb<2;++mb){
#pragma unroll
                    for(int sub=0;sub<2;++sub){
                        float* d=acc[mb][nb*2+sub];
                        MMA16816(d,ah[mb],bh[sub],bh[sub+2]);
                        MMA16816(d,ah[mb],bl[sub],bl[sub+2]);
                        MMA16816(d,al[mb],bh[sub],bh[sub+2]);
                    }
                }
            }
        }
        __syncthreads();
    }
    for(int rr=0;rr<2;++rr){
        for(int j=0;j<8;++j){
            int q=tid+j*512;
            int c=q>>5, pw=(q&31)*4;
            float4 v=*reinterpret_cast<const float4*>(
                g_yspec+((size_t)b*CC+rr*128+c)*HWX+p0+pw);
            *reinterpret_cast<float4*>(s_y+(size_t)c*YSTR+pw)=v;
        }
        __syncthreads();
        if((warp_n>>1)==rr){
#pragma unroll
            for(int mb=0;mb<2;++mb){
#pragma unroll
                for(int half=0;half<2;++half){
                    int row=warp_m*32+mb*16+half*8+(lane>>2);
#pragma unroll
                    for(int nf=0;nf<8;++nf){
                        int cl=(warp_n&1)*64+nf*8+2*(lane&3);
                        acc[mb][nf][half*2+0]+=s_y[(size_t)cl*YSTR+row];
                        acc[mb][nf][half*2+1]+=s_y[(size_t)(cl+1)*YSTR+row];
                    }
                }
            }
        }
        __syncthreads();
    }
#pragma unroll
    for(int mb=0;mb<2;++mb){
#pragma unroll
        for(int half=0;half<2;++half){
            int row=warp_m*32+mb*16+half*8+(lane>>2);
            float rs=0.0f, rq=0.0f;
#pragma unroll
            for(int nf=0;nf<8;++nf){
                int c=warp_n*64+nf*8+2*(lane&3);
                float v0=acc[mb][nf][half*2+0]+s_lb[c];
                float v1=acc[mb][nf][half*2+1]+s_lb[c+1];
                acc[mb][nf][half*2+0]=v0;
                acc[mb][nf][half*2+1]=v1;
                rs+=v0+v1; rq+=v0*v0+v1*v1;
            }
            rs+=__shfl_xor_sync(0xffffffffu,rs,1);
            rs+=__shfl_xor_sync(0xffffffffu,rs,2);
            rq+=__shfl_xor_sync(0xffffffffu,rq,1);
            rq+=__shfl_xor_sync(0xffffffffu,rq,2);
            if((lane&3)==0){
                s_sum[warp_n*128+row]=rs;
                s_sq [warp_n*128+row]=rq;
            }
        }
    }
    __syncthreads();
    if(tid<128){
        float s=0.0f,q=0.0f;
#pragma unroll
        for(int w=0;w<4;++w){ s+=s_sum[w*128+tid]; q+=s_sq[w*128+tid]; }
        float mean=s*(1.0f/256.0f);
        float var=q*(1.0f/256.0f)-mean*mean;
        s_mr[tid]=mean;
        s_mr[128+tid]=rsqrtf(var+1e-5f);
    }
    __syncthreads();
#pragma unroll
    for(int mb=0;mb<2;++mb){
#pragma unroll
        for(int half=0;half<2;++half){
            int row=warp_m*32+mb*16+half*8+(lane>>2);
            float mn=s_mr[row], rst=s_mr[128+row];
            size_t base=((size_t)b*HWX+p0+row)*CC;
#pragma unroll
            for(int nf=0;nf<8;++nf){
                int c=warp_n*64+nf*8+2*(lane&3);
                float2 o;
                o.x=s_wgt[c]  *((acc[mb][nf][half*2+0]-mn)*rst)+s_bsh[c];
                o.y=s_wgt[c+1]*((acc[mb][nf][half*2+1]-mn)*rst)+s_bsh[c+1];
                *reinterpret_cast<float2*>(out+base+c)=o;
            }
        }
    }
}

extern "C" void kernel_launch(void* const* d_in, const int* in_sizes, int n_in,
                              void* d_out, int out_size){
    const float* x      =(const float*)d_in[0];
    const float* timev  =(const float*)d_in[1];
    const float* w_real =(const float*)d_in[2];
    const float* w_imag =(const float*)d_in[3];
    const float* conv_w =(const float*)d_in[4];
    const float* lin_w  =(const float*)d_in[5];
    const float* lin_b  =(const float*)d_in[6];
    const float* mlp_w1 =(const float*)d_in[7];
    const float* mlp_b1 =(const float*)d_in[8];
    const float* mlp_w2 =(const float*)d_in[9];
    const float* mlp_b2 =(const float*)d_in[10];
    const float* norm_ww=(const float*)d_in[11];
    const float* norm_wb=(const float*)d_in[12];
    const float* norm_bw=(const float*)d_in[13];
    const float* norm_bb=(const float*)d_in[14];
    const float* kx     =(const float*)d_in[15];
    const float* ky     =(const float*)d_in[16];
    float* out=(float*)d_out;

    const int FFT_SMEM=(128*SP+64)*sizeof(float2);
    cudaFuncSetAttribute(k_fft_fwd,cudaFuncAttributeMaxDynamicSharedMemorySize,FFT_SMEM);
    cudaFuncSetAttribute(k_fft_inv,cudaFuncAttributeMaxDynamicSharedMemorySize,FFT_SMEM);
    cudaFuncSetAttribute(k_final_hmma,cudaFuncAttributeMaxDynamicSharedMemorySize,FIN_SMEM);
    cudaFuncSetAttribute(k_cgemm_hmma,cudaFuncAttributeMaxDynamicSharedMemorySize,CG_SMEM);

    k_init<<<1,1024>>>();
    {
        dim3 g(HWX/32,CC/32,BB), blk(32,8);
        k_transpose<<<g,blk>>>(x);
    }
    k_split3<<<(3*CC*CC+255)/256,256>>>(lin_w,w_real,w_imag);
    k_fft_fwd<<<BB*CC/2,512,FFT_SMEM>>>(mlp_w1,mlp_b1,mlp_w2,mlp_b2);
    {
        dim3 g((FF+63)/64,CC/128,BB);
        k_cgemm_hmma<<<g,256,CG_SMEM>>>(kx,ky);
    }
    k_fft_inv<<<BB*CC/2,1024,FFT_SMEM>>>(conv_w,kx,ky);
    {
        dim3 g(HWX/128,BB);
        k_final_hmma<<<g,512,FIN_SMEM>>>(lin_b,timev,norm_ww,norm_wb,norm_bw,norm_bb,out);
    }
}